// round 6
// baseline (speedup 1.0000x reference)
#include <cuda_runtime.h>
#include <cuda_fp16.h>
#include <cstdint>

#define BB   2
#define SS   2048
#define EE   1024
#define HH   16
#define DD   64
#define M1   4096
#define N1   3072
#define KDIM 1024
#define SCALE 0.125f

// ---------------------------------------------------------------------------
// helpers
// ---------------------------------------------------------------------------
__device__ __forceinline__ uint32_t smem_u32(const void* p) {
    uint32_t a;
    asm("{ .reg .u64 t; cvta.to.shared.u64 t, %1; cvt.u32.u64 %0, t; }" : "=r"(a) : "l"(p));
    return a;
}
#define SWZ(x) ((x) ^ (((x) >> 3) & 0x70))

#define CP16(dst, src) \
    asm volatile("cp.async.cg.shared.global [%0], [%1], 16;" :: "r"(dst), "l"(src))
#define CP_COMMIT() asm volatile("cp.async.commit_group;" ::: "memory")
#define CP_WAIT(n)  asm volatile("cp.async.wait_group %0;" :: "n"(n) : "memory")

#define LDSM4(r0,r1,r2,r3,a) \
    asm volatile("ldmatrix.sync.aligned.m8n8.x4.shared.b16 {%0,%1,%2,%3}, [%4];" \
                 : "=r"(r0),"=r"(r1),"=r"(r2),"=r"(r3) : "r"(a))
#define LDSM4T(r0,r1,r2,r3,a) \
    asm volatile("ldmatrix.sync.aligned.m8n8.x4.trans.shared.b16 {%0,%1,%2,%3}, [%4];" \
                 : "=r"(r0),"=r"(r1),"=r"(r2),"=r"(r3) : "r"(a))

// fp16 inputs, fp32 accumulate (main term)
__device__ __forceinline__ void mma_f32(float* d, const uint32_t* a, const uint32_t* b) {
    asm volatile(
        "mma.sync.aligned.m16n8k16.row.col.f32.f16.f16.f32 "
        "{%0,%1,%2,%3}, {%4,%5,%6,%7}, {%8,%9}, {%0,%1,%2,%3};"
        : "+f"(d[0]), "+f"(d[1]), "+f"(d[2]), "+f"(d[3])
        : "r"(a[0]), "r"(a[1]), "r"(a[2]), "r"(a[3]), "r"(b[0]), "r"(b[1]));
}
// fp16 inputs, fp16 accumulate (correction terms; 2 packed regs)
__device__ __forceinline__ void mma_f16(uint32_t* d, const uint32_t* a, const uint32_t* b) {
    asm volatile(
        "mma.sync.aligned.m16n8k16.row.col.f16.f16.f16.f16 "
        "{%0,%1}, {%2,%3,%4,%5}, {%6,%7}, {%0,%1};"
        : "+r"(d[0]), "+r"(d[1])
        : "r"(a[0]), "r"(a[1]), "r"(a[2]), "r"(a[3]), "r"(b[0]), "r"(b[1]));
}

__device__ __forceinline__ uint32_t packh(__half a, __half b) {
    __half2 t; t.x = a; t.y = b;
    return *reinterpret_cast<uint32_t*>(&t);
}
__device__ __forceinline__ void splitpack2(float v0, float v1, uint32_t& hi, uint32_t& lo) {
    __half h0 = __float2half_rn(v0), h1 = __float2half_rn(v1);
    __half l0 = __float2half_rn(v0 - __half2float(h0));
    __half l1 = __float2half_rn(v1 - __half2float(h1));
    hi = packh(h0, h1); lo = packh(l0, l1);
}
__device__ __forceinline__ float2 unpackh(uint32_t r) {
    __half2 h = *reinterpret_cast<__half2*>(&r);
    return __half22float2(h);
}

// ---------------------------------------------------------------------------
// scratch (__device__ globals)
// ---------------------------------------------------------------------------
#define QKV_ELEMS ((size_t)BB*HH*SS*DD)
__device__ __half g_qhi[QKV_ELEMS], g_qlo[QKV_ELEMS];
__device__ __half g_khi[QKV_ELEMS], g_klo[QKV_ELEMS];
__device__ __half g_vhi[QKV_ELEMS], g_vlo[QKV_ELEMS];
__device__ __half g_xhi[(size_t)M1*KDIM],  g_xlo[(size_t)M1*KDIM];
__device__ __half g_wqhi[(size_t)N1*KDIM], g_wqlo[(size_t)N1*KDIM];
__device__ __half g_wohi[(size_t)EE*KDIM], g_wolo[(size_t)EE*KDIM];
__device__ __half g_atthi[(size_t)M1*EE],  g_attlo[(size_t)M1*EE];

// ---------------------------------------------------------------------------
// fp32 -> fp16 hi/lo split
// ---------------------------------------------------------------------------
__global__ __launch_bounds__(256) void split_f16(const float* __restrict__ in,
                                                 __half* __restrict__ hi,
                                                 __half* __restrict__ lo,
                                                 int n4)
{
    int i = blockIdx.x * blockDim.x + threadIdx.x;
    if (i >= n4) return;
    float4 v = ((const float4*)in)[i];
    uint32_t h01, l01, h23, l23;
    splitpack2(v.x, v.y, h01, l01);
    splitpack2(v.z, v.w, h23, l23);
    ((uint2*)hi)[i] = make_uint2(h01, h23);
    ((uint2*)lo)[i] = make_uint2(l01, l23);
}

// ---------------------------------------------------------------------------
// HMMA GEMM: C = (Ahi+Alo) @ (Bhi+Blo)^T.  Main term fp32-acc; corrections
// (Ahi*Blo + Alo*Bhi) share one fp16-acc accumulator (2x-rate HMMA path).
// 128x128 tile, 16 warps (32x32), K chunks of 64, 3-stage cp.async.
// ---------------------------------------------------------------------------
#define GSTG 65536
#define GSMEM (3*GSTG)

__global__ __launch_bounds__(512, 1) void mm_mma(
    const __half* __restrict__ Ahi, const __half* __restrict__ Alo,
    const __half* __restrict__ Bhi, const __half* __restrict__ Blo,
    float* __restrict__ Cout, const float* __restrict__ bias, int mode)
{
    extern __shared__ char smc[];
    const int tid = threadIdx.x, lane = tid & 31, w = tid >> 5;
    const int wr = w >> 2, wc = w & 3;
    const int bm = blockIdx.y * 128, bn = blockIdx.x * 128;
    const uint32_t smb = smem_u32(smc);

    auto load_stage = [&](int st, int ch) {
        const int koff = ch * 64;
#pragma unroll
        for (int t = 0; t < 4; t++) {
            const __half* src = (t == 0) ? Ahi : (t == 1) ? Alo : (t == 2) ? Bhi : Blo;
            const int row0 = (t < 2) ? bm : bn;
#pragma unroll
            for (int i = 0; i < 2; i++) {
                int cid = tid + i * 512;
                int r = cid >> 3, c = cid & 7;
                uint32_t sa = smb + st * GSTG + t * 16384 + SWZ(r * 128 + c * 16);
                const char* ga = (const char*)(src + (size_t)(row0 + r) * KDIM + koff) + c * 16;
                CP16(sa, ga);
            }
        }
    };

    float acc[2][4][4];
    uint32_t crr[2][4][2];
#pragma unroll
    for (int i = 0; i < 2; i++)
#pragma unroll
        for (int j = 0; j < 4; j++) {
#pragma unroll
            for (int q = 0; q < 4; q++) acc[i][j][q] = 0.f;
            crr[i][j][0] = 0u; crr[i][j][1] = 0u;
        }

    load_stage(0, 0); CP_COMMIT();
    load_stage(1, 1); CP_COMMIT();

    const int aro  = (lane & 7) + 8 * ((lane >> 3) & 1);
    const int csel = 16 * (lane >> 4);

    for (int ch = 0; ch < 16; ch++) {
        const int st = ch % 3;
        if (ch < 15) { CP_WAIT(1); } else { CP_WAIT(0); }
        __syncthreads();
        if (ch + 2 < 16) { load_stage((ch + 2) % 3, ch + 2); CP_COMMIT(); }

        const uint32_t sAh = smb + st * GSTG;
        const uint32_t sAl = sAh + 16384;
        const uint32_t sBh = sAh + 32768;
        const uint32_t sBl = sAh + 49152;

#pragma unroll
        for (int ks = 0; ks < 4; ks++) {
            const int colb = ks * 32 + csel;
            uint32_t ah[2][4], al[2][4];
#pragma unroll
            for (int i = 0; i < 2; i++) {
                uint32_t off = SWZ((wr * 32 + i * 16 + aro) * 128 + colb);
                LDSM4(ah[i][0], ah[i][1], ah[i][2], ah[i][3], sAh + off);
                LDSM4(al[i][0], al[i][1], al[i][2], al[i][3], sAl + off);
            }
            uint32_t bhf[4][2], blf[4][2];
#pragma unroll
            for (int g = 0; g < 2; g++) {
                uint32_t off = SWZ((wc * 32 + g * 16 + aro) * 128 + colb);
                uint32_t r0, r1, r2, r3;
                LDSM4(r0, r1, r2, r3, sBh + off);
                bhf[2*g][0] = r0; bhf[2*g][1] = r2; bhf[2*g+1][0] = r1; bhf[2*g+1][1] = r3;
                LDSM4(r0, r1, r2, r3, sBl + off);
                blf[2*g][0] = r0; blf[2*g][1] = r2; blf[2*g+1][0] = r1; blf[2*g+1][1] = r3;
            }
#pragma unroll
            for (int i = 0; i < 2; i++)
#pragma unroll
                for (int j = 0; j < 4; j++) {
                    mma_f32(acc[i][j], ah[i], bhf[j]);
                    mma_f16(crr[i][j], ah[i], blf[j]);
                    mma_f16(crr[i][j], al[i], bhf[j]);
                }
        }
    }

    // epilogue: combine main + corrections
#pragma unroll
    for (int i = 0; i < 2; i++) {
        int mrow = bm + wr * 32 + i * 16 + (lane >> 2);
#pragma unroll
        for (int j = 0; j < 4; j++) {
            float2 c01 = unpackh(crr[i][j][0]);
            float2 c23 = unpackh(crr[i][j][1]);
            float v[4] = { acc[i][j][0] + c01.x, acc[i][j][1] + c01.y,
                           acc[i][j][2] + c23.x, acc[i][j][3] + c23.y };
            int n = bn + wc * 32 + j * 8 + (lane & 3) * 2;
            if (mode == 0) {
                int c = n >> 10, h = (n >> 6) & 15, d = n & 63;
                float sc = (c == 0) ? SCALE : 1.0f;
                __half* dh = (c == 0) ? g_qhi : (c == 1) ? g_khi : g_vhi;
                __half* dl = (c == 0) ? g_qlo : (c == 1) ? g_klo : g_vlo;
#pragma unroll
                for (int rr = 0; rr < 2; rr++) {
                    int m = mrow + rr * 8;
                    int b = m >> 11, s = m & 2047;
                    uint32_t hi, lo;
                    splitpack2(v[2*rr] * sc, v[2*rr + 1] * sc, hi, lo);
                    size_t idx = (((size_t)b * HH + h) * SS + s) * DD + d;
                    *(uint32_t*)&dh[idx] = hi;
                    *(uint32_t*)&dl[idx] = lo;
                }
            } else {
                float2 b2 = *(const float2*)&bias[n];
                *(float2*)&Cout[(size_t)mrow * EE + n] = make_float2(v[0] + b2.x, v[1] + b2.y);
                *(float2*)&Cout[(size_t)(mrow + 8) * EE + n] = make_float2(v[2] + b2.x, v[3] + b2.y);
            }
        }
    }
}

// ---------------------------------------------------------------------------
// FA2-style HMMA attention; corrections on fp16-acc path, per-tile combine.
// ---------------------------------------------------------------------------
#define AKV0 32768
#define ASTG 32768
#define ASMEM (AKV0 + 3*ASTG)   // 128 KB

__global__ __launch_bounds__(256, 1) void attn_mma(const int* __restrict__ mask)
{
    extern __shared__ char smc[];
    __shared__ float msk[3][64];
    const int tid = threadIdx.x, lane = tid & 31, w = tid >> 5;
    const int bh = blockIdx.y, bbi = bh >> 4, hh = bh & 15;
    const int q0 = blockIdx.x * 128;
    const uint32_t smb = smem_u32(smc);
    const uint32_t sQh = smb, sQl = smb + 16384;

    const size_t bhoff = (size_t)bh * SS * DD;
    const __half* Khg = g_khi + bhoff;
    const __half* Klg = g_klo + bhoff;
    const __half* Vhg = g_vhi + bhoff;
    const __half* Vlg = g_vlo + bhoff;
    const __half* Qhg = g_qhi + bhoff + (size_t)q0 * DD;
    const __half* Qlg = g_qlo + bhoff + (size_t)q0 * DD;

#pragma unroll
    for (int i = 0; i < 4; i++) {
        int cid = tid + i * 256;
        int r = cid >> 3, c = cid & 7;
        uint32_t so = SWZ(r * 128 + c * 16);
        CP16(sQh + so, (const char*)(Qhg + (size_t)r * DD) + c * 16);
        CP16(sQl + so, (const char*)(Qlg + (size_t)r * DD) + c * 16);
    }
    CP_COMMIT();

    auto load_kv = [&](int st, int kt) {
        uint32_t base = smb + AKV0 + st * ASTG;
        const int s0 = kt * 64;
#pragma unroll
        for (int i = 0; i < 2; i++) {
            int cid = tid + i * 256;
            int r = cid >> 3, c = cid & 7;
            uint32_t so = SWZ(r * 128 + c * 16);
            size_t go = (size_t)(s0 + r) * DD;
            CP16(base + so,         (const char*)(Khg + go) + c * 16);
            CP16(base + 8192 + so,  (const char*)(Klg + go) + c * 16);
            CP16(base + 16384 + so, (const char*)(Vhg + go) + c * 16);
            CP16(base + 24576 + so, (const char*)(Vlg + go) + c * 16);
        }
    };
    load_kv(0, 0); CP_COMMIT();
    load_kv(1, 1); CP_COMMIT();
    if (tid < 64) {
        msk[0][tid] = mask[bbi * SS + tid] ? 0.f : -1e30f;
        msk[1][tid] = mask[bbi * SS + 64 + tid] ? 0.f : -1e30f;
    }
    CP_WAIT(2);
    __syncthreads();

    const int aro  = (lane & 7) + 8 * ((lane >> 3) & 1);
    const int csel = 16 * (lane >> 4);

    uint32_t qh[4][4], ql[4][4];
#pragma unroll
    for (int ks = 0; ks < 4; ks++) {
        uint32_t off = SWZ((w * 16 + aro) * 128 + ks * 32 + csel);
        LDSM4(qh[ks][0], qh[ks][1], qh[ks][2], qh[ks][3], sQh + off);
        LDSM4(ql[ks][0], ql[ks][1], ql[ks][2], ql[ks][3], sQl + off);
    }

    float o[8][4];
#pragma unroll
    for (int j = 0; j < 8; j++)
#pragma unroll
        for (int q = 0; q < 4; q++) o[j][q] = 0.f;
    float mi0 = -1e30f, mi1 = -1e30f, li0 = 0.f, li1 = 0.f;

    for (int kt = 0; kt < 32; kt++) {
        const int st = kt % 3;
        if (kt < 31) { CP_WAIT(1); } else { CP_WAIT(0); }
        __syncthreads();
        if (kt + 2 < 32) {
            load_kv((kt + 2) % 3, kt + 2); CP_COMMIT();
            if (tid < 64)
                msk[(kt + 2) % 3][tid] = mask[bbi * SS + (kt + 2) * 64 + tid] ? 0.f : -1e30f;
        }

        const uint32_t sKh = smb + AKV0 + st * ASTG;
        const uint32_t sKl = sKh + 8192;
        const uint32_t sVh = sKh + 16384;
        const uint32_t sVl = sKh + 24576;

        // S = Q @ K^T  (main fp32-acc, corrections fp16-acc)
        float s[8][4];
        uint32_t sc[8][2];
#pragma unroll
        for (int j = 0; j < 8; j++) {
#pragma unroll
            for (int q = 0; q < 4; q++) s[j][q] = 0.f;
            sc[j][0] = 0u; sc[j][1] = 0u;
        }
#pragma unroll
        for (int ks = 0; ks < 4; ks++) {
            const int colb = ks * 32 + csel;
            uint32_t kb[8][2], kl[8][2];
#pragma unroll
            for (int g = 0; g < 4; g++) {
                uint32_t off = SWZ((g * 16 + aro) * 128 + colb);
                uint32_t r0, r1, r2, r3;
                LDSM4(r0, r1, r2, r3, sKh + off);
                kb[2*g][0] = r0; kb[2*g][1] = r2; kb[2*g+1][0] = r1; kb[2*g+1][1] = r3;
                LDSM4(r0, r1, r2, r3, sKl + off);
                kl[2*g][0] = r0; kl[2*g][1] = r2; kl[2*g+1][0] = r1; kl[2*g+1][1] = r3;
            }
#pragma unroll
            for (int j = 0; j < 8; j++) {
                mma_f32(s[j], qh[ks], kb[j]);
                mma_f16(sc[j], qh[ks], kl[j]);
                mma_f16(sc[j], ql[ks], kb[j]);
            }
        }
#pragma unroll
        for (int j = 0; j < 8; j++) {
            float2 c01 = unpackh(sc[j][0]);
            float2 c23 = unpackh(sc[j][1]);
            s[j][0] += c01.x; s[j][1] += c01.y; s[j][2] += c23.x; s[j][3] += c23.y;
        }

        // online softmax
        const int c0 = (lane & 3) * 2;
        float mn0 = mi0, mn1 = mi1;
#pragma unroll
        for (int j = 0; j < 8; j++) {
            float mk0 = msk[st][j * 8 + c0], mk1 = msk[st][j * 8 + c0 + 1];
            s[j][0] += mk0; s[j][1] += mk1; s[j][2] += mk0; s[j][3] += mk1;
            mn0 = fmaxf(mn0, fmaxf(s[j][0], s[j][1]));
            mn1 = fmaxf(mn1, fmaxf(s[j][2], s[j][3]));
        }
        mn0 = fmaxf(mn0, __shfl_xor_sync(0xffffffffu, mn0, 1));
        mn0 = fmaxf(mn0, __shfl_xor_sync(0xffffffffu, mn0, 2));
        mn1 = fmaxf(mn1, __shfl_xor_sync(0xffffffffu, mn1, 1));
        mn1 = fmaxf(mn1, __shfl_xor_sync(0xffffffffu, mn1, 2));

        float a0 = __expf(mi0 - mn0), a1 = __expf(mi1 - mn1);
        float rs0 = 0.f, rs1 = 0.f;
        uint32_t pah[4][4], pal[4][4];
#pragma unroll
        for (int j = 0; j < 8; j++) {
            float p0 = __expf(s[j][0] - mn0), p1 = __expf(s[j][1] - mn0);
            float p2 = __expf(s[j][2] - mn1), p3 = __expf(s[j][3] - mn1);
            rs0 += p0 + p1; rs1 += p2 + p3;
            uint32_t h01, l01, h23, l23;
            splitpack2(p0, p1, h01, l01);
            splitpack2(p2, p3, h23, l23);
            pah[j >> 1][2*(j & 1) + 0] = h01; pah[j >> 1][2*(j & 1) + 1] = h23;
            pal[j >> 1][2*(j & 1) + 0] = l01; pal[j >> 1][2*(j & 1) + 1] = l23;
        }
        rs0 += __shfl_xor_sync(0xffffffffu, rs0, 1);
        rs0 += __shfl_xor_sync(0xffffffffu, rs0, 2);
        rs1 += __shfl_xor_sync(0xffffffffu, rs1, 1);
        rs1 += __shfl_xor_sync(0xffffffffu, rs1, 2);
        li0 = li0 * a0 + rs0; li1 = li1 * a1 + rs1;
        mi0 = mn0; mi1 = mn1;
#pragma unroll
        for (int j = 0; j < 8; j++) {
            o[j][0] *= a0; o[j][1] *= a0; o[j][2] *= a1; o[j][3] *= a1;
        }

        // O += P @ V  (main fp32-acc, corrections fp16-acc per tile)
        uint32_t oc[8][2];
#pragma unroll
        for (int j = 0; j < 8; j++) { oc[j][0] = 0u; oc[j][1] = 0u; }
#pragma unroll
        for (int ks = 0; ks < 4; ks++) {
            uint32_t vb[8][2], vl[8][2];
#pragma unroll
            for (int dt = 0; dt < 4; dt++) {
                uint32_t off = SWZ((ks * 16 + (lane & 15)) * 128 + dt * 32 + csel);
                uint32_t r0, r1, r2, r3;
                LDSM4T(r0, r1, r2, r3, sVh + off);
                vb[2*dt][0] = r0; vb[2*dt][1] = r1; vb[2*dt+1][0] = r2; vb[2*dt+1][1] = r3;
                LDSM4T(r0, r1, r2, r3, sVl + off);
                vl[2*dt][0] = r0; vl[2*dt][1] = r1; vl[2*dt+1][0] = r2; vl[2*dt+1][1] = r3;
            }
#pragma unroll
            for (int j = 0; j < 8; j++) {
                mma_f32(o[j], pah[ks], vb[j]);
                mma_f16(oc[j], pah[ks], vl[j]);
                mma_f16(oc[j], pal[ks], vb[j]);
            }
        }
#pragma unroll
        for (int j = 0; j < 8; j++) {
            float2 c01 = unpackh(oc[j][0]);
            float2 c23 = unpackh(oc[j][1]);
            o[j][0] += c01.x; o[j][1] += c01.y; o[j][2] += c23.x; o[j][3] += c23.y;
        }
    }

    float inv0 = 1.f / li0, inv1 = 1.f / li1;
    int r0 = q0 + w * 16 + (lane >> 2);
#pragma unroll
    for (int j = 0; j < 8; j++) {
        int d = j * 8 + (lane & 3) * 2;
        uint32_t h01, l01, h23, l23;
        splitpack2(o[j][0] * inv0, o[j][1] * inv0, h01, l01);
        splitpack2(o[j][2] * inv1, o[j][3] * inv1, h23, l23);
        size_t i0 = (((size_t)bbi * SS + r0) * HH + hh) * DD + d;
        size_t i1 = (((size_t)bbi * SS + r0 + 8) * HH + hh) * DD + d;
        *(uint32_t*)&g_atthi[i0] = h01; *(uint32_t*)&g_attlo[i0] = l01;
        *(uint32_t*)&g_atthi[i1] = h23; *(uint32_t*)&g_attlo[i1] = l23;
    }
}

// ---------------------------------------------------------------------------
extern "C" void kernel_launch(void* const* d_in, const int* in_sizes, int n_in,
                              void* d_out, int out_size)
{
    const float* x     = (const float*)d_in[0];
    const int*   mask  = (const int*)  d_in[1];
    const float* qkv_w = (const float*)d_in[2];
    const float* out_w = (const float*)d_in[3];
    const float* out_b = (const float*)d_in[4];
    float*       out   = (float*)d_out;

    __half *xhi, *xlo, *wqhi, *wqlo, *wohi, *wolo, *athi, *atlo;
    cudaGetSymbolAddress((void**)&xhi,  g_xhi);  cudaGetSymbolAddress((void**)&xlo,  g_xlo);
    cudaGetSymbolAddress((void**)&wqhi, g_wqhi); cudaGetSymbolAddress((void**)&wqlo, g_wqlo);
    cudaGetSymbolAddress((void**)&wohi, g_wohi); cudaGetSymbolAddress((void**)&wolo, g_wolo);
    cudaGetSymbolAddress((void**)&athi, g_atthi); cudaGetSymbolAddress((void**)&atlo, g_attlo);

    cudaFuncSetAttribute(mm_mma,   cudaFuncAttributeMaxDynamicSharedMemorySize, GSMEM);
    cudaFuncSetAttribute(attn_mma, cudaFuncAttributeMaxDynamicSharedMemorySize, ASMEM);

    // 1) splits
    {
        int n4 = M1 * KDIM / 4;
        split_f16<<<(n4 + 255) / 256, 256>>>(x, xhi, xlo, n4);
        n4 = N1 * KDIM / 4;
        split_f16<<<(n4 + 255) / 256, 256>>>(qkv_w, wqhi, wqlo, n4);
        n4 = EE * KDIM / 4;
        split_f16<<<(n4 + 255) / 256, 256>>>(out_w, wohi, wolo, n4);
    }

    // 2) QKV projection
    {
        dim3 grid(N1 / 128, M1 / 128);
        mm_mma<<<grid, 512, GSMEM>>>(xhi, xlo, wqhi, wqlo, nullptr, nullptr, 0);
    }

    // 3) attention
    {
        dim3 grid(SS / 128, BB * HH);
        attn_mma<<<grid, 256, ASMEM>>>(mask);
    }

    // 4) output projection + bias
    {
        dim3 grid(EE / 128, M1 / 128);
        mm_mma<<<grid, 512, GSMEM>>>(athi, atlo, wohi, wolo, out, out_b, 1);
    }
}

// round 7
// speedup vs baseline: 1.3619x; 1.3619x over previous
#include <cuda_runtime.h>
#include <cuda_fp16.h>
#include <cstdint>

#define BB   2
#define SS   2048
#define EE   1024
#define HH   16
#define DD   64
#define M1   4096
#define N1   3072
#define KDIM 1024
#define SCALE 0.125f

// ---------------------------------------------------------------------------
// helpers
// ---------------------------------------------------------------------------
__device__ __forceinline__ uint32_t smem_u32(const void* p) {
    uint32_t a;
    asm("{ .reg .u64 t; cvta.to.shared.u64 t, %1; cvt.u32.u64 %0, t; }" : "=r"(a) : "l"(p));
    return a;
}
#define SWZ(x) ((x) ^ (((x) >> 3) & 0x70))

#define CP16(dst, src) \
    asm volatile("cp.async.cg.shared.global [%0], [%1], 16;" :: "r"(dst), "l"(src))
#define CP_COMMIT() asm volatile("cp.async.commit_group;" ::: "memory")
#define CP_WAIT(n)  asm volatile("cp.async.wait_group %0;" :: "n"(n) : "memory")

#define LDSM4(r0,r1,r2,r3,a) \
    asm volatile("ldmatrix.sync.aligned.m8n8.x4.shared.b16 {%0,%1,%2,%3}, [%4];" \
                 : "=r"(r0),"=r"(r1),"=r"(r2),"=r"(r3) : "r"(a))
#define LDSM4T(r0,r1,r2,r3,a) \
    asm volatile("ldmatrix.sync.aligned.m8n8.x4.trans.shared.b16 {%0,%1,%2,%3}, [%4];" \
                 : "=r"(r0),"=r"(r1),"=r"(r2),"=r"(r3) : "r"(a))

// fp16 inputs, fp32 accumulate (main term)
__device__ __forceinline__ void mma_f32(float* d, const uint32_t* a, const uint32_t* b) {
    asm volatile(
        "mma.sync.aligned.m16n8k16.row.col.f32.f16.f16.f32 "
        "{%0,%1,%2,%3}, {%4,%5,%6,%7}, {%8,%9}, {%0,%1,%2,%3};"
        : "+f"(d[0]), "+f"(d[1]), "+f"(d[2]), "+f"(d[3])
        : "r"(a[0]), "r"(a[1]), "r"(a[2]), "r"(a[3]), "r"(b[0]), "r"(b[1]));
}
// fp16 inputs, fp16 accumulate (correction term)
__device__ __forceinline__ void mma_f16(uint32_t* d, const uint32_t* a, const uint32_t* b) {
    asm volatile(
        "mma.sync.aligned.m16n8k16.row.col.f16.f16.f16.f16 "
        "{%0,%1}, {%2,%3,%4,%5}, {%6,%7}, {%0,%1};"
        : "+r"(d[0]), "+r"(d[1])
        : "r"(a[0]), "r"(a[1]), "r"(a[2]), "r"(a[3]), "r"(b[0]), "r"(b[1]));
}

__device__ __forceinline__ uint32_t packh(__half a, __half b) {
    __half2 t; t.x = a; t.y = b;
    return *reinterpret_cast<uint32_t*>(&t);
}
__device__ __forceinline__ void splitpack2(float v0, float v1, uint32_t& hi, uint32_t& lo) {
    __half h0 = __float2half_rn(v0), h1 = __float2half_rn(v1);
    __half l0 = __float2half_rn(v0 - __half2float(h0));
    __half l1 = __float2half_rn(v1 - __half2float(h1));
    hi = packh(h0, h1); lo = packh(l0, l1);
}
__device__ __forceinline__ float2 unpackh(uint32_t r) {
    __half2 h = *reinterpret_cast<__half2*>(&r);
    return __half22float2(h);
}

// ---------------------------------------------------------------------------
// scratch (__device__ globals)
// ---------------------------------------------------------------------------
#define QKV_ELEMS ((size_t)BB*HH*SS*DD)
__device__ __half g_qhi[QKV_ELEMS];
__device__ __half g_khi[QKV_ELEMS], g_klo[QKV_ELEMS];
__device__ __half g_vhi[QKV_ELEMS], g_vlo[QKV_ELEMS];
__device__ __half g_xhi[(size_t)M1*KDIM];
__device__ __half g_wqhi[(size_t)N1*KDIM], g_wqlo[(size_t)N1*KDIM];
__device__ __half g_wohi[(size_t)EE*KDIM], g_wolo[(size_t)EE*KDIM];
__device__ __half g_atthi[(size_t)M1*EE];

// ---------------------------------------------------------------------------
// fp32 -> fp16 conversions
// ---------------------------------------------------------------------------
__global__ __launch_bounds__(256) void split_f16(const float* __restrict__ in,
                                                 __half* __restrict__ hi,
                                                 __half* __restrict__ lo,
                                                 int n4)
{
    int i = blockIdx.x * blockDim.x + threadIdx.x;
    if (i >= n4) return;
    float4 v = ((const float4*)in)[i];
    uint32_t h01, l01, h23, l23;
    splitpack2(v.x, v.y, h01, l01);
    splitpack2(v.z, v.w, h23, l23);
    ((uint2*)hi)[i] = make_uint2(h01, h23);
    ((uint2*)lo)[i] = make_uint2(l01, l23);
}

__global__ __launch_bounds__(256) void conv_f16(const float* __restrict__ in,
                                                __half* __restrict__ hi, int n4)
{
    int i = blockIdx.x * blockDim.x + threadIdx.x;
    if (i >= n4) return;
    float4 v = ((const float4*)in)[i];
    uint32_t h01 = packh(__float2half_rn(v.x), __float2half_rn(v.y));
    uint32_t h23 = packh(__float2half_rn(v.z), __float2half_rn(v.w));
    ((uint2*)hi)[i] = make_uint2(h01, h23);
}

// ---------------------------------------------------------------------------
// HMMA GEMM (2-term lossy split): C = Ahi @ (Bhi+Blo)^T.
// 128x128 tile, 16 warps (32x32), K chunks of 64, 3-stage cp.async.
// mode 0: scatter q (hi), k/v (hi+lo); mode 1: fp32 out + bias.
// ---------------------------------------------------------------------------
#define GSTG 49152           // Ahi + Bhi + Blo, 16KB each
#define GSMEM (3*GSTG)

__global__ __launch_bounds__(512, 1) void mm_mma(
    const __half* __restrict__ Ahi,
    const __half* __restrict__ Bhi, const __half* __restrict__ Blo,
    float* __restrict__ Cout, const float* __restrict__ bias, int mode)
{
    extern __shared__ char smc[];
    const int tid = threadIdx.x, lane = tid & 31, w = tid >> 5;
    const int wr = w >> 2, wc = w & 3;
    const int bm = blockIdx.y * 128, bn = blockIdx.x * 128;
    const uint32_t smb = smem_u32(smc);

    auto load_stage = [&](int st, int ch) {
        const int koff = ch * 64;
#pragma unroll
        for (int t = 0; t < 3; t++) {
            const __half* src = (t == 0) ? Ahi : (t == 1) ? Bhi : Blo;
            const int row0 = (t == 0) ? bm : bn;
#pragma unroll
            for (int i = 0; i < 2; i++) {
                int cid = tid + i * 512;
                int r = cid >> 3, c = cid & 7;
                uint32_t sa = smb + st * GSTG + t * 16384 + SWZ(r * 128 + c * 16);
                const char* ga = (const char*)(src + (size_t)(row0 + r) * KDIM + koff) + c * 16;
                CP16(sa, ga);
            }
        }
    };

    float acc[2][4][4];
    uint32_t crr[2][4][2];
#pragma unroll
    for (int i = 0; i < 2; i++)
#pragma unroll
        for (int j = 0; j < 4; j++) {
#pragma unroll
            for (int q = 0; q < 4; q++) acc[i][j][q] = 0.f;
            crr[i][j][0] = 0u; crr[i][j][1] = 0u;
        }

    load_stage(0, 0); CP_COMMIT();
    load_stage(1, 1); CP_COMMIT();

    const int aro  = (lane & 7) + 8 * ((lane >> 3) & 1);
    const int csel = 16 * (lane >> 4);

    for (int ch = 0; ch < 16; ch++) {
        const int st = ch % 3;
        if (ch < 15) { CP_WAIT(1); } else { CP_WAIT(0); }
        __syncthreads();
        if (ch + 2 < 16) { load_stage((ch + 2) % 3, ch + 2); CP_COMMIT(); }

        const uint32_t sAh = smb + st * GSTG;
        const uint32_t sBh = sAh + 16384;
        const uint32_t sBl = sAh + 32768;

#pragma unroll
        for (int ks = 0; ks < 4; ks++) {
            const int colb = ks * 32 + csel;
            uint32_t ah[2][4];
#pragma unroll
            for (int i = 0; i < 2; i++) {
                uint32_t off = SWZ((wr * 32 + i * 16 + aro) * 128 + colb);
                LDSM4(ah[i][0], ah[i][1], ah[i][2], ah[i][3], sAh + off);
            }
            uint32_t bhf[4][2], blf[4][2];
#pragma unroll
            for (int g = 0; g < 2; g++) {
                uint32_t off = SWZ((wc * 32 + g * 16 + aro) * 128 + colb);
                uint32_t r0, r1, r2, r3;
                LDSM4(r0, r1, r2, r3, sBh + off);
                bhf[2*g][0] = r0; bhf[2*g][1] = r2; bhf[2*g+1][0] = r1; bhf[2*g+1][1] = r3;
                LDSM4(r0, r1, r2, r3, sBl + off);
                blf[2*g][0] = r0; blf[2*g][1] = r2; blf[2*g+1][0] = r1; blf[2*g+1][1] = r3;
            }
#pragma unroll
            for (int i = 0; i < 2; i++)
#pragma unroll
                for (int j = 0; j < 4; j++) {
                    mma_f32(acc[i][j], ah[i], bhf[j]);
                    mma_f16(crr[i][j], ah[i], blf[j]);
                }
        }
    }

    // epilogue: combine main + correction
#pragma unroll
    for (int i = 0; i < 2; i++) {
        int mrow = bm + wr * 32 + i * 16 + (lane >> 2);
#pragma unroll
        for (int j = 0; j < 4; j++) {
            float2 c01 = unpackh(crr[i][j][0]);
            float2 c23 = unpackh(crr[i][j][1]);
            float v[4] = { acc[i][j][0] + c01.x, acc[i][j][1] + c01.y,
                           acc[i][j][2] + c23.x, acc[i][j][3] + c23.y };
            int n = bn + wc * 32 + j * 8 + (lane & 3) * 2;
            if (mode == 0) {
                int c = n >> 10, h = (n >> 6) & 15, d = n & 63;
#pragma unroll
                for (int rr = 0; rr < 2; rr++) {
                    int m = mrow + rr * 8;
                    int b = m >> 11, s = m & 2047;
                    size_t idx = (((size_t)b * HH + h) * SS + s) * DD + d;
                    if (c == 0) {
                        uint32_t hi = packh(__float2half_rn(v[2*rr] * SCALE),
                                            __float2half_rn(v[2*rr + 1] * SCALE));
                        *(uint32_t*)&g_qhi[idx] = hi;
                    } else {
                        __half* dh = (c == 1) ? g_khi : g_vhi;
                        __half* dl = (c == 1) ? g_klo : g_vlo;
                        uint32_t hi, lo;
                        splitpack2(v[2*rr], v[2*rr + 1], hi, lo);
                        *(uint32_t*)&dh[idx] = hi;
                        *(uint32_t*)&dl[idx] = lo;
                    }
                }
            } else {
                float2 b2 = *(const float2*)&bias[n];
                *(float2*)&Cout[(size_t)mrow * EE + n] = make_float2(v[0] + b2.x, v[1] + b2.y);
                *(float2*)&Cout[(size_t)(mrow + 8) * EE + n] = make_float2(v[2] + b2.x, v[3] + b2.y);
            }
        }
    }
}

// ---------------------------------------------------------------------------
// FA2-style HMMA attention (2-term): S = qhi·(khi+klo), O = phi·(vhi+vlo).
// ---------------------------------------------------------------------------
#define AKV0 16384
#define ASTG 32768
#define ASMEM (AKV0 + 3*ASTG)   // 112 KB

__global__ __launch_bounds__(256, 1) void attn_mma(const int* __restrict__ mask)
{
    extern __shared__ char smc[];
    __shared__ float msk[3][64];
    const int tid = threadIdx.x, lane = tid & 31, w = tid >> 5;
    const int bh = blockIdx.y, bbi = bh >> 4, hh = bh & 15;
    const int q0 = blockIdx.x * 128;
    const uint32_t smb = smem_u32(smc);
    const uint32_t sQh = smb;

    const size_t bhoff = (size_t)bh * SS * DD;
    const __half* Khg = g_khi + bhoff;
    const __half* Klg = g_klo + bhoff;
    const __half* Vhg = g_vhi + bhoff;
    const __half* Vlg = g_vlo + bhoff;
    const __half* Qhg = g_qhi + bhoff + (size_t)q0 * DD;

#pragma unroll
    for (int i = 0; i < 4; i++) {
        int cid = tid + i * 256;
        int r = cid >> 3, c = cid & 7;
        uint32_t so = SWZ(r * 128 + c * 16);
        CP16(sQh + so, (const char*)(Qhg + (size_t)r * DD) + c * 16);
    }
    CP_COMMIT();

    auto load_kv = [&](int st, int kt) {
        uint32_t base = smb + AKV0 + st * ASTG;
        const int s0 = kt * 64;
#pragma unroll
        for (int i = 0; i < 2; i++) {
            int cid = tid + i * 256;
            int r = cid >> 3, c = cid & 7;
            uint32_t so = SWZ(r * 128 + c * 16);
            size_t go = (size_t)(s0 + r) * DD;
            CP16(base + so,         (const char*)(Khg + go) + c * 16);
            CP16(base + 8192 + so,  (const char*)(Klg + go) + c * 16);
            CP16(base + 16384 + so, (const char*)(Vhg + go) + c * 16);
            CP16(base + 24576 + so, (const char*)(Vlg + go) + c * 16);
        }
    };
    load_kv(0, 0); CP_COMMIT();
    load_kv(1, 1); CP_COMMIT();
    if (tid < 64) {
        msk[0][tid] = mask[bbi * SS + tid] ? 0.f : -1e30f;
        msk[1][tid] = mask[bbi * SS + 64 + tid] ? 0.f : -1e30f;
    }
    CP_WAIT(2);
    __syncthreads();

    const int aro  = (lane & 7) + 8 * ((lane >> 3) & 1);
    const int csel = 16 * (lane >> 4);

    uint32_t qh[4][4];
#pragma unroll
    for (int ks = 0; ks < 4; ks++) {
        uint32_t off = SWZ((w * 16 + aro) * 128 + ks * 32 + csel);
        LDSM4(qh[ks][0], qh[ks][1], qh[ks][2], qh[ks][3], sQh + off);
    }

    float o[8][4];
#pragma unroll
    for (int j = 0; j < 8; j++)
#pragma unroll
        for (int q = 0; q < 4; q++) o[j][q] = 0.f;
    float mi0 = -1e30f, mi1 = -1e30f, li0 = 0.f, li1 = 0.f;

    for (int kt = 0; kt < 32; kt++) {
        const int st = kt % 3;
        if (kt < 31) { CP_WAIT(1); } else { CP_WAIT(0); }
        __syncthreads();
        if (kt + 2 < 32) {
            load_kv((kt + 2) % 3, kt + 2); CP_COMMIT();
            if (tid < 64)
                msk[(kt + 2) % 3][tid] = mask[bbi * SS + (kt + 2) * 64 + tid] ? 0.f : -1e30f;
        }

        const uint32_t sKh = smb + AKV0 + st * ASTG;
        const uint32_t sKl = sKh + 8192;
        const uint32_t sVh = sKh + 16384;
        const uint32_t sVl = sKh + 24576;

        // S = qhi @ (khi + klo)^T
        float s[8][4];
        uint32_t sc[8][2];
#pragma unroll
        for (int j = 0; j < 8; j++) {
#pragma unroll
            for (int q = 0; q < 4; q++) s[j][q] = 0.f;
            sc[j][0] = 0u; sc[j][1] = 0u;
        }
#pragma unroll
        for (int ks = 0; ks < 4; ks++) {
            const int colb = ks * 32 + csel;
            uint32_t kb[8][2], kl[8][2];
#pragma unroll
            for (int g = 0; g < 4; g++) {
                uint32_t off = SWZ((g * 16 + aro) * 128 + colb);
                uint32_t r0, r1, r2, r3;
                LDSM4(r0, r1, r2, r3, sKh + off);
                kb[2*g][0] = r0; kb[2*g][1] = r2; kb[2*g+1][0] = r1; kb[2*g+1][1] = r3;
                LDSM4(r0, r1, r2, r3, sKl + off);
                kl[2*g][0] = r0; kl[2*g][1] = r2; kl[2*g+1][0] = r1; kl[2*g+1][1] = r3;
            }
#pragma unroll
            for (int j = 0; j < 8; j++) {
                mma_f32(s[j], qh[ks], kb[j]);
                mma_f16(sc[j], qh[ks], kl[j]);
            }
        }
#pragma unroll
        for (int j = 0; j < 8; j++) {
            float2 c01 = unpackh(sc[j][0]);
            float2 c23 = unpackh(sc[j][1]);
            s[j][0] += c01.x; s[j][1] += c01.y; s[j][2] += c23.x; s[j][3] += c23.y;
        }

        // online softmax
        const int c0 = (lane & 3) * 2;
        float mn0 = mi0, mn1 = mi1;
#pragma unroll
        for (int j = 0; j < 8; j++) {
            float mk0 = msk[st][j * 8 + c0], mk1 = msk[st][j * 8 + c0 + 1];
            s[j][0] += mk0; s[j][1] += mk1; s[j][2] += mk0; s[j][3] += mk1;
            mn0 = fmaxf(mn0, fmaxf(s[j][0], s[j][1]));
            mn1 = fmaxf(mn1, fmaxf(s[j][2], s[j][3]));
        }
        mn0 = fmaxf(mn0, __shfl_xor_sync(0xffffffffu, mn0, 1));
        mn0 = fmaxf(mn0, __shfl_xor_sync(0xffffffffu, mn0, 2));
        mn1 = fmaxf(mn1, __shfl_xor_sync(0xffffffffu, mn1, 1));
        mn1 = fmaxf(mn1, __shfl_xor_sync(0xffffffffu, mn1, 2));

        float a0 = __expf(mi0 - mn0), a1 = __expf(mi1 - mn1);
        float rs0 = 0.f, rs1 = 0.f;
        uint32_t pah[4][4];
#pragma unroll
        for (int j = 0; j < 8; j++) {
            float p0 = __expf(s[j][0] - mn0), p1 = __expf(s[j][1] - mn0);
            float p2 = __expf(s[j][2] - mn1), p3 = __expf(s[j][3] - mn1);
            rs0 += p0 + p1; rs1 += p2 + p3;
            pah[j >> 1][2*(j & 1) + 0] = packh(__float2half_rn(p0), __float2half_rn(p1));
            pah[j >> 1][2*(j & 1) + 1] = packh(__float2half_rn(p2), __float2half_rn(p3));
        }
        rs0 += __shfl_xor_sync(0xffffffffu, rs0, 1);
        rs0 += __shfl_xor_sync(0xffffffffu, rs0, 2);
        rs1 += __shfl_xor_sync(0xffffffffu, rs1, 1);
        rs1 += __shfl_xor_sync(0xffffffffu, rs1, 2);
        li0 = li0 * a0 + rs0; li1 = li1 * a1 + rs1;
        mi0 = mn0; mi1 = mn1;
#pragma unroll
        for (int j = 0; j < 8; j++) {
            o[j][0] *= a0; o[j][1] *= a0; o[j][2] *= a1; o[j][3] *= a1;
        }

        // O += phi @ (vhi + vlo)
        uint32_t oc[8][2];
#pragma unroll
        for (int j = 0; j < 8; j++) { oc[j][0] = 0u; oc[j][1] = 0u; }
#pragma unroll
        for (int ks = 0; ks < 4; ks++) {
            uint32_t vb[8][2], vl[8][2];
#pragma unroll
            for (int dt = 0; dt < 4; dt++) {
                uint32_t off = SWZ((ks * 16 + (lane & 15)) * 128 + dt * 32 + csel);
                uint32_t r0, r1, r2, r3;
                LDSM4T(r0, r1, r2, r3, sVh + off);
                vb[2*dt][0] = r0; vb[2*dt][1] = r1; vb[2*dt+1][0] = r2; vb[2*dt+1][1] = r3;
                LDSM4T(r0, r1, r2, r3, sVl + off);
                vl[2*dt][0] = r0; vl[2*dt][1] = r1; vl[2*dt+1][0] = r2; vl[2*dt+1][1] = r3;
            }
#pragma unroll
            for (int j = 0; j < 8; j++) {
                mma_f32(o[j], pah[ks], vb[j]);
                mma_f16(oc[j], pah[ks], vl[j]);
            }
        }
#pragma unroll
        for (int j = 0; j < 8; j++) {
            float2 c01 = unpackh(oc[j][0]);
            float2 c23 = unpackh(oc[j][1]);
            o[j][0] += c01.x; o[j][1] += c01.y; o[j][2] += c23.x; o[j][3] += c23.y;
        }
    }

    float inv0 = 1.f / li0, inv1 = 1.f / li1;
    int r0 = q0 + w * 16 + (lane >> 2);
#pragma unroll
    for (int j = 0; j < 8; j++) {
        int d = j * 8 + (lane & 3) * 2;
        uint32_t h01 = packh(__float2half_rn(o[j][0] * inv0), __float2half_rn(o[j][1] * inv0));
        uint32_t h23 = packh(__float2half_rn(o[j][2] * inv1), __float2half_rn(o[j][3] * inv1));
        size_t i0 = (((size_t)bbi * SS + r0) * HH + hh) * DD + d;
        size_t i1 = (((size_t)bbi * SS + r0 + 8) * HH + hh) * DD + d;
        *(uint32_t*)&g_atthi[i0] = h01;
        *(uint32_t*)&g_atthi[i1] = h23;
    }
}

// ---------------------------------------------------------------------------
extern "C" void kernel_launch(void* const* d_in, const int* in_sizes, int n_in,
                              void* d_out, int out_size)
{
    const float* x     = (const float*)d_in[0];
    const int*   mask  = (const int*)  d_in[1];
    const float* qkv_w = (const float*)d_in[2];
    const float* out_w = (const float*)d_in[3];
    const float* out_b = (const float*)d_in[4];
    float*       out   = (float*)d_out;

    __half *xhi, *wqhi, *wqlo, *wohi, *wolo, *athi;
    cudaGetSymbolAddress((void**)&xhi,  g_xhi);
    cudaGetSymbolAddress((void**)&wqhi, g_wqhi); cudaGetSymbolAddress((void**)&wqlo, g_wqlo);
    cudaGetSymbolAddress((void**)&wohi, g_wohi); cudaGetSymbolAddress((void**)&wolo, g_wolo);
    cudaGetSymbolAddress((void**)&athi, g_atthi);

    cudaFuncSetAttribute(mm_mma,   cudaFuncAttributeMaxDynamicSharedMemorySize, GSMEM);
    cudaFuncSetAttribute(attn_mma, cudaFuncAttributeMaxDynamicSharedMemorySize, ASMEM);

    // 1) conversions / splits
    {
        int n4 = M1 * KDIM / 4;
        conv_f16<<<(n4 + 255) / 256, 256>>>(x, xhi, n4);
        n4 = N1 * KDIM / 4;
        split_f16<<<(n4 + 255) / 256, 256>>>(qkv_w, wqhi, wqlo, n4);
        n4 = EE * KDIM / 4;
        split_f16<<<(n4 + 255) / 256, 256>>>(out_w, wohi, wolo, n4);
    }

    // 2) QKV projection
    {
        dim3 grid(N1 / 128, M1 / 128);
        mm_mma<<<grid, 512, GSMEM>>>(xhi, wqhi, wqlo, nullptr, nullptr, 0);
    }

    // 3) attention
    {
        dim3 grid(SS / 128, BB * HH);
        attn_mma<<<grid, 256, ASMEM>>>(mask);
    }

    // 4) output projection + bias
    {
        dim3 grid(EE / 128, M1 / 128);
        mm_mma<<<grid, 512, GSMEM>>>(athi, wohi, wolo, out, out_b, 1);
    }
}

// round 8
// speedup vs baseline: 1.7511x; 1.2858x over previous
#include <cuda_runtime.h>
#include <cuda_fp16.h>
#include <cstdint>

#define BB   2
#define SS   2048
#define EE   1024
#define HH   16
#define DD   64
#define M1   4096
#define N1   3072
#define KDIM 1024
#define SCALE 0.125f

// ---------------------------------------------------------------------------
// helpers
// ---------------------------------------------------------------------------
__device__ __forceinline__ uint32_t smem_u32(const void* p) {
    uint32_t a;
    asm("{ .reg .u64 t; cvta.to.shared.u64 t, %1; cvt.u32.u64 %0, t; }" : "=r"(a) : "l"(p));
    return a;
}
#define SWZ(x) ((x) ^ (((x) >> 3) & 0x70))

#define CP16(dst, src) \
    asm volatile("cp.async.cg.shared.global [%0], [%1], 16;" :: "r"(dst), "l"(src))
#define CP_COMMIT() asm volatile("cp.async.commit_group;" ::: "memory")
#define CP_WAIT(n)  asm volatile("cp.async.wait_group %0;" :: "n"(n) : "memory")

#define LDSM4(r0,r1,r2,r3,a) \
    asm volatile("ldmatrix.sync.aligned.m8n8.x4.shared.b16 {%0,%1,%2,%3}, [%4];" \
                 : "=r"(r0),"=r"(r1),"=r"(r2),"=r"(r3) : "r"(a))
#define LDSM4T(r0,r1,r2,r3,a) \
    asm volatile("ldmatrix.sync.aligned.m8n8.x4.trans.shared.b16 {%0,%1,%2,%3}, [%4];" \
                 : "=r"(r0),"=r"(r1),"=r"(r2),"=r"(r3) : "r"(a))

// fp16 inputs, fp32 accumulate (main term)
__device__ __forceinline__ void mma_f32(float* d, const uint32_t* a, const uint32_t* b) {
    asm volatile(
        "mma.sync.aligned.m16n8k16.row.col.f32.f16.f16.f32 "
        "{%0,%1,%2,%3}, {%4,%5,%6,%7}, {%8,%9}, {%0,%1,%2,%3};"
        : "+f"(d[0]), "+f"(d[1]), "+f"(d[2]), "+f"(d[3])
        : "r"(a[0]), "r"(a[1]), "r"(a[2]), "r"(a[3]), "r"(b[0]), "r"(b[1]));
}
// fp16 inputs, fp16 accumulate (correction term)
__device__ __forceinline__ void mma_f16(uint32_t* d, const uint32_t* a, const uint32_t* b) {
    asm volatile(
        "mma.sync.aligned.m16n8k16.row.col.f16.f16.f16.f16 "
        "{%0,%1}, {%2,%3,%4,%5}, {%6,%7}, {%0,%1};"
        : "+r"(d[0]), "+r"(d[1])
        : "r"(a[0]), "r"(a[1]), "r"(a[2]), "r"(a[3]), "r"(b[0]), "r"(b[1]));
}

__device__ __forceinline__ uint32_t packh(__half a, __half b) {
    __half2 t; t.x = a; t.y = b;
    return *reinterpret_cast<uint32_t*>(&t);
}
__device__ __forceinline__ void splitpack2(float v0, float v1, uint32_t& hi, uint32_t& lo) {
    __half h0 = __float2half_rn(v0), h1 = __float2half_rn(v1);
    __half l0 = __float2half_rn(v0 - __half2float(h0));
    __half l1 = __float2half_rn(v1 - __half2float(h1));
    hi = packh(h0, h1); lo = packh(l0, l1);
}
__device__ __forceinline__ float2 unpackh(uint32_t r) {
    __half2 h = *reinterpret_cast<__half2*>(&r);
    return __half22float2(h);
}

// ---------------------------------------------------------------------------
// scratch (__device__ globals)
// ---------------------------------------------------------------------------
#define QKV_ELEMS ((size_t)BB*HH*SS*DD)
__device__ __half g_qhi[QKV_ELEMS];
__device__ __half g_khi[QKV_ELEMS];
__device__ __half g_vhi[QKV_ELEMS];
__device__ __half g_xhi[(size_t)M1*KDIM];
__device__ __half g_wqhi[(size_t)N1*KDIM], g_wqlo[(size_t)N1*KDIM];
__device__ __half g_wohi[(size_t)EE*KDIM], g_wolo[(size_t)EE*KDIM];
__device__ __half g_atthi[(size_t)M1*EE];

// ---------------------------------------------------------------------------
// fp32 -> fp16 conversions
// ---------------------------------------------------------------------------
__global__ __launch_bounds__(256) void split_f16(const float* __restrict__ in,
                                                 __half* __restrict__ hi,
                                                 __half* __restrict__ lo,
                                                 int n4)
{
    int i = blockIdx.x * blockDim.x + threadIdx.x;
    if (i >= n4) return;
    float4 v = ((const float4*)in)[i];
    uint32_t h01, l01, h23, l23;
    splitpack2(v.x, v.y, h01, l01);
    splitpack2(v.z, v.w, h23, l23);
    ((uint2*)hi)[i] = make_uint2(h01, h23);
    ((uint2*)lo)[i] = make_uint2(l01, l23);
}

__global__ __launch_bounds__(256) void conv_f16(const float* __restrict__ in,
                                                __half* __restrict__ hi, int n4)
{
    int i = blockIdx.x * blockDim.x + threadIdx.x;
    if (i >= n4) return;
    float4 v = ((const float4*)in)[i];
    uint32_t h01 = packh(__float2half_rn(v.x), __float2half_rn(v.y));
    uint32_t h23 = packh(__float2half_rn(v.z), __float2half_rn(v.w));
    ((uint2*)hi)[i] = make_uint2(h01, h23);
}

// ---------------------------------------------------------------------------
// HMMA GEMM (2-term lossy split): C = Ahi @ (Bhi+Blo)^T.
// 128x128 tile, 16 warps (32x32), K chunks of 64, 3-stage cp.async.
// mode 0: scatter q/k/v as plain fp16 (q scaled); mode 1: fp32 out + bias.
// ---------------------------------------------------------------------------
#define GSTG 49152           // Ahi + Bhi + Blo, 16KB each
#define GSMEM (3*GSTG)

__global__ __launch_bounds__(512, 1) void mm_mma(
    const __half* __restrict__ Ahi,
    const __half* __restrict__ Bhi, const __half* __restrict__ Blo,
    float* __restrict__ Cout, const float* __restrict__ bias, int mode)
{
    extern __shared__ char smc[];
    const int tid = threadIdx.x, lane = tid & 31, w = tid >> 5;
    const int wr = w >> 2, wc = w & 3;
    const int bm = blockIdx.y * 128, bn = blockIdx.x * 128;
    const uint32_t smb = smem_u32(smc);

    auto load_stage = [&](int st, int ch) {
        const int koff = ch * 64;
#pragma unroll
        for (int t = 0; t < 3; t++) {
            const __half* src = (t == 0) ? Ahi : (t == 1) ? Bhi : Blo;
            const int row0 = (t == 0) ? bm : bn;
#pragma unroll
            for (int i = 0; i < 2; i++) {
                int cid = tid + i * 512;
                int r = cid >> 3, c = cid & 7;
                uint32_t sa = smb + st * GSTG + t * 16384 + SWZ(r * 128 + c * 16);
                const char* ga = (const char*)(src + (size_t)(row0 + r) * KDIM + koff) + c * 16;
                CP16(sa, ga);
            }
        }
    };

    float acc[2][4][4];
    uint32_t crr[2][4][2];
#pragma unroll
    for (int i = 0; i < 2; i++)
#pragma unroll
        for (int j = 0; j < 4; j++) {
#pragma unroll
            for (int q = 0; q < 4; q++) acc[i][j][q] = 0.f;
            crr[i][j][0] = 0u; crr[i][j][1] = 0u;
        }

    load_stage(0, 0); CP_COMMIT();
    load_stage(1, 1); CP_COMMIT();

    const int aro  = (lane & 7) + 8 * ((lane >> 3) & 1);
    const int csel = 16 * (lane >> 4);

    for (int ch = 0; ch < 16; ch++) {
        const int st = ch % 3;
        if (ch < 15) { CP_WAIT(1); } else { CP_WAIT(0); }
        __syncthreads();
        if (ch + 2 < 16) { load_stage((ch + 2) % 3, ch + 2); CP_COMMIT(); }

        const uint32_t sAh = smb + st * GSTG;
        const uint32_t sBh = sAh + 16384;
        const uint32_t sBl = sAh + 32768;

#pragma unroll
        for (int ks = 0; ks < 4; ks++) {
            const int colb = ks * 32 + csel;
            uint32_t ah[2][4];
#pragma unroll
            for (int i = 0; i < 2; i++) {
                uint32_t off = SWZ((wr * 32 + i * 16 + aro) * 128 + colb);
                LDSM4(ah[i][0], ah[i][1], ah[i][2], ah[i][3], sAh + off);
            }
            uint32_t bhf[4][2], blf[4][2];
#pragma unroll
            for (int g = 0; g < 2; g++) {
                uint32_t off = SWZ((wc * 32 + g * 16 + aro) * 128 + colb);
                uint32_t r0, r1, r2, r3;
                LDSM4(r0, r1, r2, r3, sBh + off);
                bhf[2*g][0] = r0; bhf[2*g][1] = r2; bhf[2*g+1][0] = r1; bhf[2*g+1][1] = r3;
                LDSM4(r0, r1, r2, r3, sBl + off);
                blf[2*g][0] = r0; blf[2*g][1] = r2; blf[2*g+1][0] = r1; blf[2*g+1][1] = r3;
            }
#pragma unroll
            for (int i = 0; i < 2; i++)
#pragma unroll
                for (int j = 0; j < 4; j++) {
                    mma_f32(acc[i][j], ah[i], bhf[j]);
                    mma_f16(crr[i][j], ah[i], blf[j]);
                }
        }
    }

    // epilogue: combine main + correction
#pragma unroll
    for (int i = 0; i < 2; i++) {
        int mrow = bm + wr * 32 + i * 16 + (lane >> 2);
#pragma unroll
        for (int j = 0; j < 4; j++) {
            float2 c01 = unpackh(crr[i][j][0]);
            float2 c23 = unpackh(crr[i][j][1]);
            float v[4] = { acc[i][j][0] + c01.x, acc[i][j][1] + c01.y,
                           acc[i][j][2] + c23.x, acc[i][j][3] + c23.y };
            int n = bn + wc * 32 + j * 8 + (lane & 3) * 2;
            if (mode == 0) {
                int c = n >> 10, h = (n >> 6) & 15, d = n & 63;
                float sc = (c == 0) ? SCALE : 1.0f;
                __half* dst = (c == 0) ? g_qhi : (c == 1) ? g_khi : g_vhi;
#pragma unroll
                for (int rr = 0; rr < 2; rr++) {
                    int m = mrow + rr * 8;
                    int b = m >> 11, s = m & 2047;
                    size_t idx = (((size_t)b * HH + h) * SS + s) * DD + d;
                    uint32_t hv = packh(__float2half_rn(v[2*rr] * sc),
                                        __float2half_rn(v[2*rr + 1] * sc));
                    *(uint32_t*)&dst[idx] = hv;
                }
            } else {
                float2 b2 = *(const float2*)&bias[n];
                *(float2*)&Cout[(size_t)mrow * EE + n] = make_float2(v[0] + b2.x, v[1] + b2.y);
                *(float2*)&Cout[(size_t)(mrow + 8) * EE + n] = make_float2(v[2] + b2.x, v[3] + b2.y);
            }
        }
    }
}

// ---------------------------------------------------------------------------
// FA2-style HMMA attention (pure fp16 KV): S = qhi·khi, O = phi·vhi.
// KV stage = 16KB (K 8KB + V 8KB). smem total 64KB -> 2 CTAs/SM.
// ---------------------------------------------------------------------------
#define AKV0 16384
#define ASTG 16384
#define ASMEM (AKV0 + 3*ASTG)   // 64 KB

__global__ __launch_bounds__(256, 2) void attn_mma(const int* __restrict__ mask)
{
    extern __shared__ char smc[];
    __shared__ float msk[3][64];
    const int tid = threadIdx.x, lane = tid & 31, w = tid >> 5;
    const int bh = blockIdx.y, bbi = bh >> 4, hh = bh & 15;
    const int q0 = blockIdx.x * 128;
    const uint32_t smb = smem_u32(smc);
    const uint32_t sQh = smb;

    const size_t bhoff = (size_t)bh * SS * DD;
    const __half* Khg = g_khi + bhoff;
    const __half* Vhg = g_vhi + bhoff;
    const __half* Qhg = g_qhi + bhoff + (size_t)q0 * DD;

    // Q tile 128x64 fp16 = 16KB
#pragma unroll
    for (int i = 0; i < 4; i++) {
        int cid = tid + i * 256;
        int r = cid >> 3, c = cid & 7;
        uint32_t so = SWZ(r * 128 + c * 16);
        CP16(sQh + so, (const char*)(Qhg + (size_t)r * DD) + c * 16);
    }
    CP_COMMIT();

    auto load_kv = [&](int st, int kt) {
        uint32_t base = smb + AKV0 + st * ASTG;
        const int s0 = kt * 64;
#pragma unroll
        for (int i = 0; i < 2; i++) {
            int cid = tid + i * 256;       // 0..511 covers 64 rows x 8 cols
            int r = cid >> 3, c = cid & 7;
            uint32_t so = SWZ(r * 128 + c * 16);
            size_t go = (size_t)(s0 + r) * DD;
            CP16(base + so,        (const char*)(Khg + go) + c * 16);
            CP16(base + 8192 + so, (const char*)(Vhg + go) + c * 16);
        }
    };
    load_kv(0, 0); CP_COMMIT();
    load_kv(1, 1); CP_COMMIT();
    if (tid < 64) {
        msk[0][tid] = mask[bbi * SS + tid] ? 0.f : -1e30f;
        msk[1][tid] = mask[bbi * SS + 64 + tid] ? 0.f : -1e30f;
    }
    CP_WAIT(2);
    __syncthreads();

    const int aro  = (lane & 7) + 8 * ((lane >> 3) & 1);
    const int csel = 16 * (lane >> 4);

    uint32_t qh[4][4];
#pragma unroll
    for (int ks = 0; ks < 4; ks++) {
        uint32_t off = SWZ((w * 16 + aro) * 128 + ks * 32 + csel);
        LDSM4(qh[ks][0], qh[ks][1], qh[ks][2], qh[ks][3], sQh + off);
    }

    float o[8][4];
#pragma unroll
    for (int j = 0; j < 8; j++)
#pragma unroll
        for (int q = 0; q < 4; q++) o[j][q] = 0.f;
    float mi0 = -1e30f, mi1 = -1e30f, li0 = 0.f, li1 = 0.f;

    for (int kt = 0; kt < 32; kt++) {
        const int st = kt % 3;
        if (kt < 31) { CP_WAIT(1); } else { CP_WAIT(0); }
        __syncthreads();
        if (kt + 2 < 32) {
            load_kv((kt + 2) % 3, kt + 2); CP_COMMIT();
            if (tid < 64)
                msk[(kt + 2) % 3][tid] = mask[bbi * SS + (kt + 2) * 64 + tid] ? 0.f : -1e30f;
        }

        const uint32_t sKh = smb + AKV0 + st * ASTG;
        const uint32_t sVh = sKh + 8192;

        // S = qhi @ khi^T
        float s[8][4];
#pragma unroll
        for (int j = 0; j < 8; j++)
#pragma unroll
            for (int q = 0; q < 4; q++) s[j][q] = 0.f;
#pragma unroll
        for (int ks = 0; ks < 4; ks++) {
            const int colb = ks * 32 + csel;
            uint32_t kb[8][2];
#pragma unroll
            for (int g = 0; g < 4; g++) {
                uint32_t off = SWZ((g * 16 + aro) * 128 + colb);
                uint32_t r0, r1, r2, r3;
                LDSM4(r0, r1, r2, r3, sKh + off);
                kb[2*g][0] = r0; kb[2*g][1] = r2; kb[2*g+1][0] = r1; kb[2*g+1][1] = r3;
            }
#pragma unroll
            for (int j = 0; j < 8; j++)
                mma_f32(s[j], qh[ks], kb[j]);
        }

        // online softmax
        const int c0 = (lane & 3) * 2;
        float mn0 = mi0, mn1 = mi1;
#pragma unroll
        for (int j = 0; j < 8; j++) {
            float mk0 = msk[st][j * 8 + c0], mk1 = msk[st][j * 8 + c0 + 1];
            s[j][0] += mk0; s[j][1] += mk1; s[j][2] += mk0; s[j][3] += mk1;
            mn0 = fmaxf(mn0, fmaxf(s[j][0], s[j][1]));
            mn1 = fmaxf(mn1, fmaxf(s[j][2], s[j][3]));
        }
        mn0 = fmaxf(mn0, __shfl_xor_sync(0xffffffffu, mn0, 1));
        mn0 = fmaxf(mn0, __shfl_xor_sync(0xffffffffu, mn0, 2));
        mn1 = fmaxf(mn1, __shfl_xor_sync(0xffffffffu, mn1, 1));
        mn1 = fmaxf(mn1, __shfl_xor_sync(0xffffffffu, mn1, 2));

        float a0 = __expf(mi0 - mn0), a1 = __expf(mi1 - mn1);
        float rs0 = 0.f, rs1 = 0.f;
        uint32_t pah[4][4];
#pragma unroll
        for (int j = 0; j < 8; j++) {
            float p0 = __expf(s[j][0] - mn0), p1 = __expf(s[j][1] - mn0);
            float p2 = __expf(s[j][2] - mn1), p3 = __expf(s[j][3] - mn1);
            rs0 += p0 + p1; rs1 += p2 + p3;
            pah[j >> 1][2*(j & 1) + 0] = packh(__float2half_rn(p0), __float2half_rn(p1));
            pah[j >> 1][2*(j & 1) + 1] = packh(__float2half_rn(p2), __float2half_rn(p3));
        }
        rs0 += __shfl_xor_sync(0xffffffffu, rs0, 1);
        rs0 += __shfl_xor_sync(0xffffffffu, rs0, 2);
        rs1 += __shfl_xor_sync(0xffffffffu, rs1, 1);
        rs1 += __shfl_xor_sync(0xffffffffu, rs1, 2);
        li0 = li0 * a0 + rs0; li1 = li1 * a1 + rs1;
        mi0 = mn0; mi1 = mn1;
#pragma unroll
        for (int j = 0; j < 8; j++) {
            o[j][0] *= a0; o[j][1] *= a0; o[j][2] *= a1; o[j][3] *= a1;
        }

        // O += phi @ vhi
#pragma unroll
        for (int ks = 0; ks < 4; ks++) {
            uint32_t vb[8][2];
#pragma unroll
            for (int dt = 0; dt < 4; dt++) {
                uint32_t off = SWZ((ks * 16 + (lane & 15)) * 128 + dt * 32 + csel);
                uint32_t r0, r1, r2, r3;
                LDSM4T(r0, r1, r2, r3, sVh + off);
                vb[2*dt][0] = r0; vb[2*dt][1] = r1; vb[2*dt+1][0] = r2; vb[2*dt+1][1] = r3;
            }
#pragma unroll
            for (int j = 0; j < 8; j++)
                mma_f32(o[j], pah[ks], vb[j]);
        }
    }

    float inv0 = 1.f / li0, inv1 = 1.f / li1;
    int r0 = q0 + w * 16 + (lane >> 2);
#pragma unroll
    for (int j = 0; j < 8; j++) {
        int d = j * 8 + (lane & 3) * 2;
        uint32_t h01 = packh(__float2half_rn(o[j][0] * inv0), __float2half_rn(o[j][1] * inv0));
        uint32_t h23 = packh(__float2half_rn(o[j][2] * inv1), __float2half_rn(o[j][3] * inv1));
        size_t i0 = (((size_t)bbi * SS + r0) * HH + hh) * DD + d;
        size_t i1 = (((size_t)bbi * SS + r0 + 8) * HH + hh) * DD + d;
        *(uint32_t*)&g_atthi[i0] = h01;
        *(uint32_t*)&g_atthi[i1] = h23;
    }
}

// ---------------------------------------------------------------------------
extern "C" void kernel_launch(void* const* d_in, const int* in_sizes, int n_in,
                              void* d_out, int out_size)
{
    const float* x     = (const float*)d_in[0];
    const int*   mask  = (const int*)  d_in[1];
    const float* qkv_w = (const float*)d_in[2];
    const float* out_w = (const float*)d_in[3];
    const float* out_b = (const float*)d_in[4];
    float*       out   = (float*)d_out;

    __half *xhi, *wqhi, *wqlo, *wohi, *wolo, *athi;
    cudaGetSymbolAddress((void**)&xhi,  g_xhi);
    cudaGetSymbolAddress((void**)&wqhi, g_wqhi); cudaGetSymbolAddress((void**)&wqlo, g_wqlo);
    cudaGetSymbolAddress((void**)&wohi, g_wohi); cudaGetSymbolAddress((void**)&wolo, g_wolo);
    cudaGetSymbolAddress((void**)&athi, g_atthi);

    cudaFuncSetAttribute(mm_mma,   cudaFuncAttributeMaxDynamicSharedMemorySize, GSMEM);
    cudaFuncSetAttribute(attn_mma, cudaFuncAttributeMaxDynamicSharedMemorySize, ASMEM);

    // 1) conversions / splits
    {
        int n4 = M1 * KDIM / 4;
        conv_f16<<<(n4 + 255) / 256, 256>>>(x, xhi, n4);
        n4 = N1 * KDIM / 4;
        split_f16<<<(n4 + 255) / 256, 256>>>(qkv_w, wqhi, wqlo, n4);
        n4 = EE * KDIM / 4;
        split_f16<<<(n4 + 255) / 256, 256>>>(out_w, wohi, wolo, n4);
    }

    // 2) QKV projection
    {
        dim3 grid(N1 / 128, M1 / 128);
        mm_mma<<<grid, 512, GSMEM>>>(xhi, wqhi, wqlo, nullptr, nullptr, 0);
    }

    // 3) attention
    {
        dim3 grid(SS / 128, BB * HH);
        attn_mma<<<grid, 256, ASMEM>>>(mask);
    }

    // 4) output projection + bias
    {
        dim3 grid(EE / 128, M1 / 128);
        mm_mma<<<grid, 512, GSMEM>>>(athi, wohi, wolo, out, out_b, 1);
    }
}

// round 9
// speedup vs baseline: 2.3977x; 1.3693x over previous
#include <cuda_runtime.h>
#include <cuda_fp16.h>
#include <cstdint>

#define BB   2
#define SS   2048
#define EE   1024
#define HH   16
#define DD   64
#define M1   4096
#define N1   3072
#define KDIM 1024
#define SCALE 0.125f

// ---------------------------------------------------------------------------
// helpers
// ---------------------------------------------------------------------------
__device__ __forceinline__ uint32_t smem_u32(const void* p) {
    uint32_t a;
    asm("{ .reg .u64 t; cvta.to.shared.u64 t, %1; cvt.u32.u64 %0, t; }" : "=r"(a) : "l"(p));
    return a;
}
#define SWZ(x) ((x) ^ (((x) >> 3) & 0x70))

#define CP16(dst, src) \
    asm volatile("cp.async.cg.shared.global [%0], [%1], 16;" :: "r"(dst), "l"(src))
#define CP_COMMIT() asm volatile("cp.async.commit_group;" ::: "memory")
#define CP_WAIT(n)  asm volatile("cp.async.wait_group %0;" :: "n"(n) : "memory")

#define LDSM4(r0,r1,r2,r3,a) \
    asm volatile("ldmatrix.sync.aligned.m8n8.x4.shared.b16 {%0,%1,%2,%3}, [%4];" \
                 : "=r"(r0),"=r"(r1),"=r"(r2),"=r"(r3) : "r"(a))
#define LDSM4T(r0,r1,r2,r3,a) \
    asm volatile("ldmatrix.sync.aligned.m8n8.x4.trans.shared.b16 {%0,%1,%2,%3}, [%4];" \
                 : "=r"(r0),"=r"(r1),"=r"(r2),"=r"(r3) : "r"(a))

// fp16 inputs, fp32 accumulate
__device__ __forceinline__ void mma_f32(float* d, const uint32_t* a, const uint32_t* b) {
    asm volatile(
        "mma.sync.aligned.m16n8k16.row.col.f32.f16.f16.f32 "
        "{%0,%1,%2,%3}, {%4,%5,%6,%7}, {%8,%9}, {%0,%1,%2,%3};"
        : "+f"(d[0]), "+f"(d[1]), "+f"(d[2]), "+f"(d[3])
        : "r"(a[0]), "r"(a[1]), "r"(a[2]), "r"(a[3]), "r"(b[0]), "r"(b[1]));
}

__device__ __forceinline__ uint32_t packh(__half a, __half b) {
    __half2 t; t.x = a; t.y = b;
    return *reinterpret_cast<uint32_t*>(&t);
}

// ---------------------------------------------------------------------------
// scratch (__device__ globals)
// ---------------------------------------------------------------------------
#define QKV_ELEMS ((size_t)BB*HH*SS*DD)
__device__ __half g_qhi[QKV_ELEMS];
__device__ __half g_khi[QKV_ELEMS];
__device__ __half g_vhi[QKV_ELEMS];
__device__ __half g_xhi[(size_t)M1*KDIM];
__device__ __half g_wqhi[(size_t)N1*KDIM];
__device__ __half g_wohi[(size_t)EE*KDIM];
__device__ __half g_atthi[(size_t)M1*EE];

// ---------------------------------------------------------------------------
// fp32 -> fp16 convert
// ---------------------------------------------------------------------------
__global__ __launch_bounds__(256) void conv_f16(const float* __restrict__ in,
                                                __half* __restrict__ hi, int n4)
{
    int i = blockIdx.x * blockDim.x + threadIdx.x;
    if (i >= n4) return;
    float4 v = ((const float4*)in)[i];
    uint32_t h01 = packh(__float2half_rn(v.x), __float2half_rn(v.y));
    uint32_t h23 = packh(__float2half_rn(v.z), __float2half_rn(v.w));
    ((uint2*)hi)[i] = make_uint2(h01, h23);
}

// ---------------------------------------------------------------------------
// HMMA GEMM (pure fp16 in / fp32 acc): C = A @ B^T.
// 128x128 tile, 16 warps (32x32), K chunks of 64, 3-stage cp.async.
// mode 0: scatter q/k/v as fp16 (q scaled); mode 1: fp32 out + bias.
// ---------------------------------------------------------------------------
#define GSTG 32768           // A + B, 16KB each
#define GSMEM (3*GSTG)

__global__ __launch_bounds__(512, 1) void mm_mma(
    const __half* __restrict__ A, const __half* __restrict__ B,
    float* __restrict__ Cout, const float* __restrict__ bias, int mode)
{
    extern __shared__ char smc[];
    const int tid = threadIdx.x, lane = tid & 31, w = tid >> 5;
    const int wr = w >> 2, wc = w & 3;
    const int bm = blockIdx.y * 128, bn = blockIdx.x * 128;
    const uint32_t smb = smem_u32(smc);

    auto load_stage = [&](int st, int ch) {
        const int koff = ch * 64;
#pragma unroll
        for (int t = 0; t < 2; t++) {
            const __half* src = (t == 0) ? A : B;
            const int row0 = (t == 0) ? bm : bn;
#pragma unroll
            for (int i = 0; i < 2; i++) {
                int cid = tid + i * 512;
                int r = cid >> 3, c = cid & 7;
                uint32_t sa = smb + st * GSTG + t * 16384 + SWZ(r * 128 + c * 16);
                const char* ga = (const char*)(src + (size_t)(row0 + r) * KDIM + koff) + c * 16;
                CP16(sa, ga);
            }
        }
    };

    float acc[2][4][4];
#pragma unroll
    for (int i = 0; i < 2; i++)
#pragma unroll
        for (int j = 0; j < 4; j++)
#pragma unroll
            for (int q = 0; q < 4; q++) acc[i][j][q] = 0.f;

    load_stage(0, 0); CP_COMMIT();
    load_stage(1, 1); CP_COMMIT();

    const int aro  = (lane & 7) + 8 * ((lane >> 3) & 1);
    const int csel = 16 * (lane >> 4);

    for (int ch = 0; ch < 16; ch++) {
        const int st = ch % 3;
        if (ch < 15) { CP_WAIT(1); } else { CP_WAIT(0); }
        __syncthreads();
        if (ch + 2 < 16) { load_stage((ch + 2) % 3, ch + 2); CP_COMMIT(); }

        const uint32_t sA = smb + st * GSTG;
        const uint32_t sB = sA + 16384;

#pragma unroll
        for (int ks = 0; ks < 4; ks++) {
            const int colb = ks * 32 + csel;
            uint32_t ah[2][4];
#pragma unroll
            for (int i = 0; i < 2; i++) {
                uint32_t off = SWZ((wr * 32 + i * 16 + aro) * 128 + colb);
                LDSM4(ah[i][0], ah[i][1], ah[i][2], ah[i][3], sA + off);
            }
            uint32_t bhf[4][2];
#pragma unroll
            for (int g = 0; g < 2; g++) {
                uint32_t off = SWZ((wc * 32 + g * 16 + aro) * 128 + colb);
                uint32_t r0, r1, r2, r3;
                LDSM4(r0, r1, r2, r3, sB + off);
                bhf[2*g][0] = r0; bhf[2*g][1] = r2; bhf[2*g+1][0] = r1; bhf[2*g+1][1] = r3;
            }
#pragma unroll
            for (int i = 0; i < 2; i++)
#pragma unroll
                for (int j = 0; j < 4; j++)
                    mma_f32(acc[i][j], ah[i], bhf[j]);
        }
    }

    // epilogue
#pragma unroll
    for (int i = 0; i < 2; i++) {
        int mrow = bm + wr * 32 + i * 16 + (lane >> 2);
#pragma unroll
        for (int j = 0; j < 4; j++) {
            int n = bn + wc * 32 + j * 8 + (lane & 3) * 2;
            if (mode == 0) {
                int c = n >> 10, h = (n >> 6) & 15, d = n & 63;
                float sc = (c == 0) ? SCALE : 1.0f;
                __half* dst = (c == 0) ? g_qhi : (c == 1) ? g_khi : g_vhi;
#pragma unroll
                for (int rr = 0; rr < 2; rr++) {
                    int m = mrow + rr * 8;
                    int b = m >> 11, s = m & 2047;
                    size_t idx = (((size_t)b * HH + h) * SS + s) * DD + d;
                    uint32_t hv = packh(__float2half_rn(acc[i][j][2*rr] * sc),
                                        __float2half_rn(acc[i][j][2*rr + 1] * sc));
                    *(uint32_t*)&dst[idx] = hv;
                }
            } else {
                float2 b2 = *(const float2*)&bias[n];
                *(float2*)&Cout[(size_t)mrow * EE + n] =
                    make_float2(acc[i][j][0] + b2.x, acc[i][j][1] + b2.y);
                *(float2*)&Cout[(size_t)(mrow + 8) * EE + n] =
                    make_float2(acc[i][j][2] + b2.x, acc[i][j][3] + b2.y);
            }
        }
    }
}

// ---------------------------------------------------------------------------
// FA2-style HMMA attention (pure fp16 KV), unchanged from round 8.
// ---------------------------------------------------------------------------
#define AKV0 16384
#define ASTG 16384
#define ASMEM (AKV0 + 3*ASTG)   // 64 KB

__global__ __launch_bounds__(256, 2) void attn_mma(const int* __restrict__ mask)
{
    extern __shared__ char smc[];
    __shared__ float msk[3][64];
    const int tid = threadIdx.x, lane = tid & 31, w = tid >> 5;
    const int bh = blockIdx.y, bbi = bh >> 4, hh = bh & 15;
    const int q0 = blockIdx.x * 128;
    const uint32_t smb = smem_u32(smc);
    const uint32_t sQh = smb;

    const size_t bhoff = (size_t)bh * SS * DD;
    const __half* Khg = g_khi + bhoff;
    const __half* Vhg = g_vhi + bhoff;
    const __half* Qhg = g_qhi + bhoff + (size_t)q0 * DD;

#pragma unroll
    for (int i = 0; i < 4; i++) {
        int cid = tid + i * 256;
        int r = cid >> 3, c = cid & 7;
        uint32_t so = SWZ(r * 128 + c * 16);
        CP16(sQh + so, (const char*)(Qhg + (size_t)r * DD) + c * 16);
    }
    CP_COMMIT();

    auto load_kv = [&](int st, int kt) {
        uint32_t base = smb + AKV0 + st * ASTG;
        const int s0 = kt * 64;
#pragma unroll
        for (int i = 0; i < 2; i++) {
            int cid = tid + i * 256;
            int r = cid >> 3, c = cid & 7;
            uint32_t so = SWZ(r * 128 + c * 16);
            size_t go = (size_t)(s0 + r) * DD;
            CP16(base + so,        (const char*)(Khg + go) + c * 16);
            CP16(base + 8192 + so, (const char*)(Vhg + go) + c * 16);
        }
    };
    load_kv(0, 0); CP_COMMIT();
    load_kv(1, 1); CP_COMMIT();
    if (tid < 64) {
        msk[0][tid] = mask[bbi * SS + tid] ? 0.f : -1e30f;
        msk[1][tid] = mask[bbi * SS + 64 + tid] ? 0.f : -1e30f;
    }
    CP_WAIT(2);
    __syncthreads();

    const int aro  = (lane & 7) + 8 * ((lane >> 3) & 1);
    const int csel = 16 * (lane >> 4);

    uint32_t qh[4][4];
#pragma unroll
    for (int ks = 0; ks < 4; ks++) {
        uint32_t off = SWZ((w * 16 + aro) * 128 + ks * 32 + csel);
        LDSM4(qh[ks][0], qh[ks][1], qh[ks][2], qh[ks][3], sQh + off);
    }

    float o[8][4];
#pragma unroll
    for (int j = 0; j < 8; j++)
#pragma unroll
        for (int q = 0; q < 4; q++) o[j][q] = 0.f;
    float mi0 = -1e30f, mi1 = -1e30f, li0 = 0.f, li1 = 0.f;

    for (int kt = 0; kt < 32; kt++) {
        const int st = kt % 3;
        if (kt < 31) { CP_WAIT(1); } else { CP_WAIT(0); }
        __syncthreads();
        if (kt + 2 < 32) {
            load_kv((kt + 2) % 3, kt + 2); CP_COMMIT();
            if (tid < 64)
                msk[(kt + 2) % 3][tid] = mask[bbi * SS + (kt + 2) * 64 + tid] ? 0.f : -1e30f;
        }

        const uint32_t sKh = smb + AKV0 + st * ASTG;
        const uint32_t sVh = sKh + 8192;

        // S = q @ k^T
        float s[8][4];
#pragma unroll
        for (int j = 0; j < 8; j++)
#pragma unroll
            for (int q = 0; q < 4; q++) s[j][q] = 0.f;
#pragma unroll
        for (int ks = 0; ks < 4; ks++) {
            const int colb = ks * 32 + csel;
            uint32_t kb[8][2];
#pragma unroll
            for (int g = 0; g < 4; g++) {
                uint32_t off = SWZ((g * 16 + aro) * 128 + colb);
                uint32_t r0, r1, r2, r3;
                LDSM4(r0, r1, r2, r3, sKh + off);
                kb[2*g][0] = r0; kb[2*g][1] = r2; kb[2*g+1][0] = r1; kb[2*g+1][1] = r3;
            }
#pragma unroll
            for (int j = 0; j < 8; j++)
                mma_f32(s[j], qh[ks], kb[j]);
        }

        // online softmax
        const int c0 = (lane & 3) * 2;
        float mn0 = mi0, mn1 = mi1;
#pragma unroll
        for (int j = 0; j < 8; j++) {
            float mk0 = msk[st][j * 8 + c0], mk1 = msk[st][j * 8 + c0 + 1];
            s[j][0] += mk0; s[j][1] += mk1; s[j][2] += mk0; s[j][3] += mk1;
            mn0 = fmaxf(mn0, fmaxf(s[j][0], s[j][1]));
            mn1 = fmaxf(mn1, fmaxf(s[j][2], s[j][3]));
        }
        mn0 = fmaxf(mn0, __shfl_xor_sync(0xffffffffu, mn0, 1));
        mn0 = fmaxf(mn0, __shfl_xor_sync(0xffffffffu, mn0, 2));
        mn1 = fmaxf(mn1, __shfl_xor_sync(0xffffffffu, mn1, 1));
        mn1 = fmaxf(mn1, __shfl_xor_sync(0xffffffffu, mn1, 2));

        float a0 = __expf(mi0 - mn0), a1 = __expf(mi1 - mn1);
        float rs0 = 0.f, rs1 = 0.f;
        uint32_t pah[4][4];
#pragma unroll
        for (int j = 0; j < 8; j++) {
            float p0 = __expf(s[j][0] - mn0), p1 = __expf(s[j][1] - mn0);
            float p2 = __expf(s[j][2] - mn1), p3 = __expf(s[j][3] - mn1);
            rs0 += p0 + p1; rs1 += p2 + p3;
            pah[j >> 1][2*(j & 1) + 0] = packh(__float2half_rn(p0), __float2half_rn(p1));
            pah[j >> 1][2*(j & 1) + 1] = packh(__float2half_rn(p2), __float2half_rn(p3));
        }
        rs0 += __shfl_xor_sync(0xffffffffu, rs0, 1);
        rs0 += __shfl_xor_sync(0xffffffffu, rs0, 2);
        rs1 += __shfl_xor_sync(0xffffffffu, rs1, 1);
        rs1 += __shfl_xor_sync(0xffffffffu, rs1, 2);
        li0 = li0 * a0 + rs0; li1 = li1 * a1 + rs1;
        mi0 = mn0; mi1 = mn1;
#pragma unroll
        for (int j = 0; j < 8; j++) {
            o[j][0] *= a0; o[j][1] *= a0; o[j][2] *= a1; o[j][3] *= a1;
        }

        // O += p @ v
#pragma unroll
        for (int ks = 0; ks < 4; ks++) {
            uint32_t vb[8][2];
#pragma unroll
            for (int dt = 0; dt < 4; dt++) {
                uint32_t off = SWZ((ks * 16 + (lane & 15)) * 128 + dt * 32 + csel);
                uint32_t r0, r1, r2, r3;
                LDSM4T(r0, r1, r2, r3, sVh + off);
                vb[2*dt][0] = r0; vb[2*dt][1] = r1; vb[2*dt+1][0] = r2; vb[2*dt+1][1] = r3;
            }
#pragma unroll
            for (int j = 0; j < 8; j++)
                mma_f32(o[j], pah[ks], vb[j]);
        }
    }

    float inv0 = 1.f / li0, inv1 = 1.f / li1;
    int r0 = q0 + w * 16 + (lane >> 2);
#pragma unroll
    for (int j = 0; j < 8; j++) {
        int d = j * 8 + (lane & 3) * 2;
        uint32_t h01 = packh(__float2half_rn(o[j][0] * inv0), __float2half_rn(o[j][1] * inv0));
        uint32_t h23 = packh(__float2half_rn(o[j][2] * inv1), __float2half_rn(o[j][3] * inv1));
        size_t i0 = (((size_t)bbi * SS + r0) * HH + hh) * DD + d;
        size_t i1 = (((size_t)bbi * SS + r0 + 8) * HH + hh) * DD + d;
        *(uint32_t*)&g_atthi[i0] = h01;
        *(uint32_t*)&g_atthi[i1] = h23;
    }
}

// ---------------------------------------------------------------------------
extern "C" void kernel_launch(void* const* d_in, const int* in_sizes, int n_in,
                              void* d_out, int out_size)
{
    const float* x     = (const float*)d_in[0];
    const int*   mask  = (const int*)  d_in[1];
    const float* qkv_w = (const float*)d_in[2];
    const float* out_w = (const float*)d_in[3];
    const float* out_b = (const float*)d_in[4];
    float*       out   = (float*)d_out;

    __half *xhi, *wqhi, *wohi, *athi;
    cudaGetSymbolAddress((void**)&xhi,  g_xhi);
    cudaGetSymbolAddress((void**)&wqhi, g_wqhi);
    cudaGetSymbolAddress((void**)&wohi, g_wohi);
    cudaGetSymbolAddress((void**)&athi, g_atthi);

    cudaFuncSetAttribute(mm_mma,   cudaFuncAttributeMaxDynamicSharedMemorySize, GSMEM);
    cudaFuncSetAttribute(attn_mma, cudaFuncAttributeMaxDynamicSharedMemorySize, ASMEM);

    // 1) conversions
    {
        int n4 = M1 * KDIM / 4;
        conv_f16<<<(n4 + 255) / 256, 256>>>(x, xhi, n4);
        n4 = N1 * KDIM / 4;
        conv_f16<<<(n4 + 255) / 256, 256>>>(qkv_w, wqhi, n4);
        n4 = EE * KDIM / 4;
        conv_f16<<<(n4 + 255) / 256, 256>>>(out_w, wohi, n4);
    }

    // 2) QKV projection
    {
        dim3 grid(N1 / 128, M1 / 128);
        mm_mma<<<grid, 512, GSMEM>>>(xhi, wqhi, nullptr, nullptr, 0);
    }

    // 3) attention
    {
        dim3 grid(SS / 128, BB * HH);
        attn_mma<<<grid, 256, ASMEM>>>(mask);
    }

    // 4) output projection + bias
    {
        dim3 grid(EE / 128, M1 / 128);
        mm_mma<<<grid, 512, GSMEM>>>(athi, wohi, out, out_b, 1);
    }
}

// round 10
// speedup vs baseline: 2.5316x; 1.0558x over previous
#include <cuda_runtime.h>
#include <cuda_fp16.h>
#include <cstdint>

#define BB   2
#define SS   2048
#define EE   1024
#define HH   16
#define DD   64
#define M1   4096
#define N1   3072
#define KDIM 1024
#define SCALE 0.125f
#define L2E  1.4426950408889634f

// ---------------------------------------------------------------------------
// helpers
// ---------------------------------------------------------------------------
__device__ __forceinline__ uint32_t smem_u32(const void* p) {
    uint32_t a;
    asm("{ .reg .u64 t; cvta.to.shared.u64 t, %1; cvt.u32.u64 %0, t; }" : "=r"(a) : "l"(p));
    return a;
}
#define SWZ(x) ((x) ^ (((x) >> 3) & 0x70))

#define CP16(dst, src) \
    asm volatile("cp.async.cg.shared.global [%0], [%1], 16;" :: "r"(dst), "l"(src))
#define CP_COMMIT() asm volatile("cp.async.commit_group;" ::: "memory")
#define CP_WAIT(n)  asm volatile("cp.async.wait_group %0;" :: "n"(n) : "memory")

#define LDSM4(r0,r1,r2,r3,a) \
    asm volatile("ldmatrix.sync.aligned.m8n8.x4.shared.b16 {%0,%1,%2,%3}, [%4];" \
                 : "=r"(r0),"=r"(r1),"=r"(r2),"=r"(r3) : "r"(a))
#define LDSM4T(r0,r1,r2,r3,a) \
    asm volatile("ldmatrix.sync.aligned.m8n8.x4.trans.shared.b16 {%0,%1,%2,%3}, [%4];" \
                 : "=r"(r0),"=r"(r1),"=r"(r2),"=r"(r3) : "r"(a))

// fp16 inputs, fp32 accumulate
__device__ __forceinline__ void mma_f32(float* d, const uint32_t* a, const uint32_t* b) {
    asm volatile(
        "mma.sync.aligned.m16n8k16.row.col.f32.f16.f16.f32 "
        "{%0,%1,%2,%3}, {%4,%5,%6,%7}, {%8,%9}, {%0,%1,%2,%3};"
        : "+f"(d[0]), "+f"(d[1]), "+f"(d[2]), "+f"(d[3])
        : "r"(a[0]), "r"(a[1]), "r"(a[2]), "r"(a[3]), "r"(b[0]), "r"(b[1]));
}

__device__ __forceinline__ uint32_t packh(__half a, __half b) {
    __half2 t; t.x = a; t.y = b;
    return *reinterpret_cast<uint32_t*>(&t);
}

// pack (lo,hi) f32 pair -> half2, then 2^x on both lanes
__device__ __forceinline__ uint32_t exp2_f16x2(float lo, float hi) {
    uint32_t r;
    asm("cvt.rn.f16x2.f32 %0, %1, %2;" : "=r"(r) : "f"(hi), "f"(lo));
    asm("ex2.approx.f16x2 %0, %0;" : "+r"(r));
    return r;
}

// ---------------------------------------------------------------------------
// scratch (__device__ globals)
// ---------------------------------------------------------------------------
#define QKV_ELEMS ((size_t)BB*HH*SS*DD)
__device__ __half g_qhi[QKV_ELEMS];
__device__ __half g_khi[QKV_ELEMS];
__device__ __half g_vhi[QKV_ELEMS];
__device__ __half g_xhi[(size_t)M1*KDIM];
__device__ __half g_wqhi[(size_t)N1*KDIM];
__device__ __half g_wohi[(size_t)EE*KDIM];
__device__ __half g_atthi[(size_t)M1*EE];

// ---------------------------------------------------------------------------
// fp32 -> fp16 convert
// ---------------------------------------------------------------------------
__global__ __launch_bounds__(256) void conv_f16(const float* __restrict__ in,
                                                __half* __restrict__ hi, int n4)
{
    int i = blockIdx.x * blockDim.x + threadIdx.x;
    if (i >= n4) return;
    float4 v = ((const float4*)in)[i];
    uint32_t h01 = packh(__float2half_rn(v.x), __float2half_rn(v.y));
    uint32_t h23 = packh(__float2half_rn(v.z), __float2half_rn(v.w));
    ((uint2*)hi)[i] = make_uint2(h01, h23);
}

// ---------------------------------------------------------------------------
// HMMA GEMM (pure fp16 in / fp32 acc): C = A @ B^T.  (unchanged from R9)
// ---------------------------------------------------------------------------
#define GSTG 32768
#define GSMEM (3*GSTG)

__global__ __launch_bounds__(512, 1) void mm_mma(
    const __half* __restrict__ A, const __half* __restrict__ B,
    float* __restrict__ Cout, const float* __restrict__ bias, int mode)
{
    extern __shared__ char smc[];
    const int tid = threadIdx.x, lane = tid & 31, w = tid >> 5;
    const int wr = w >> 2, wc = w & 3;
    const int bm = blockIdx.y * 128, bn = blockIdx.x * 128;
    const uint32_t smb = smem_u32(smc);

    auto load_stage = [&](int st, int ch) {
        const int koff = ch * 64;
#pragma unroll
        for (int t = 0; t < 2; t++) {
            const __half* src = (t == 0) ? A : B;
            const int row0 = (t == 0) ? bm : bn;
#pragma unroll
            for (int i = 0; i < 2; i++) {
                int cid = tid + i * 512;
                int r = cid >> 3, c = cid & 7;
                uint32_t sa = smb + st * GSTG + t * 16384 + SWZ(r * 128 + c * 16);
                const char* ga = (const char*)(src + (size_t)(row0 + r) * KDIM + koff) + c * 16;
                CP16(sa, ga);
            }
        }
    };

    float acc[2][4][4];
#pragma unroll
    for (int i = 0; i < 2; i++)
#pragma unroll
        for (int j = 0; j < 4; j++)
#pragma unroll
            for (int q = 0; q < 4; q++) acc[i][j][q] = 0.f;

    load_stage(0, 0); CP_COMMIT();
    load_stage(1, 1); CP_COMMIT();

    const int aro  = (lane & 7) + 8 * ((lane >> 3) & 1);
    const int csel = 16 * (lane >> 4);

    for (int ch = 0; ch < 16; ch++) {
        const int st = ch % 3;
        if (ch < 15) { CP_WAIT(1); } else { CP_WAIT(0); }
        __syncthreads();
        if (ch + 2 < 16) { load_stage((ch + 2) % 3, ch + 2); CP_COMMIT(); }

        const uint32_t sA = smb + st * GSTG;
        const uint32_t sB = sA + 16384;

#pragma unroll
        for (int ks = 0; ks < 4; ks++) {
            const int colb = ks * 32 + csel;
            uint32_t ah[2][4];
#pragma unroll
            for (int i = 0; i < 2; i++) {
                uint32_t off = SWZ((wr * 32 + i * 16 + aro) * 128 + colb);
                LDSM4(ah[i][0], ah[i][1], ah[i][2], ah[i][3], sA + off);
            }
            uint32_t bhf[4][2];
#pragma unroll
            for (int g = 0; g < 2; g++) {
                uint32_t off = SWZ((wc * 32 + g * 16 + aro) * 128 + colb);
                uint32_t r0, r1, r2, r3;
                LDSM4(r0, r1, r2, r3, sB + off);
                bhf[2*g][0] = r0; bhf[2*g][1] = r2; bhf[2*g+1][0] = r1; bhf[2*g+1][1] = r3;
            }
#pragma unroll
            for (int i = 0; i < 2; i++)
#pragma unroll
                for (int j = 0; j < 4; j++)
                    mma_f32(acc[i][j], ah[i], bhf[j]);
        }
    }

#pragma unroll
    for (int i = 0; i < 2; i++) {
        int mrow = bm + wr * 32 + i * 16 + (lane >> 2);
#pragma unroll
        for (int j = 0; j < 4; j++) {
            int n = bn + wc * 32 + j * 8 + (lane & 3) * 2;
            if (mode == 0) {
                int c = n >> 10, h = (n >> 6) & 15, d = n & 63;
                float sc = (c == 0) ? SCALE : 1.0f;
                __half* dst = (c == 0) ? g_qhi : (c == 1) ? g_khi : g_vhi;
#pragma unroll
                for (int rr = 0; rr < 2; rr++) {
                    int m = mrow + rr * 8;
                    int b = m >> 11, s = m & 2047;
                    size_t idx = (((size_t)b * HH + h) * SS + s) * DD + d;
                    uint32_t hv = packh(__float2half_rn(acc[i][j][2*rr] * sc),
                                        __float2half_rn(acc[i][j][2*rr + 1] * sc));
                    *(uint32_t*)&dst[idx] = hv;
                }
            } else {
                float2 b2 = *(const float2*)&bias[n];
                *(float2*)&Cout[(size_t)mrow * EE + n] =
                    make_float2(acc[i][j][0] + b2.x, acc[i][j][1] + b2.y);
                *(float2*)&Cout[(size_t)(mrow + 8) * EE + n] =
                    make_float2(acc[i][j][2] + b2.x, acc[i][j][3] + b2.y);
            }
        }
    }
}

// ---------------------------------------------------------------------------
// FA2-style HMMA attention.
//  - grid (8, 32): each CTA does 2 q-blocks (single wave at 2 CTAs/SM)
//  - softmax exp via ex2.approx.f16x2 (result IS the packed P fragment)
//  - row sums via ones-MMA into f32 accumulators (no shuffles, exact)
// ---------------------------------------------------------------------------
#define AKV0 16384
#define ASTG 16384
#define ASMEM (AKV0 + 3*ASTG)   // 64 KB

__global__ __launch_bounds__(256, 2) void attn_mma(const int* __restrict__ mask)
{
    extern __shared__ char smc[];
    __shared__ float msk[3][64];
    const int tid = threadIdx.x, lane = tid & 31, w = tid >> 5;
    const int bh = blockIdx.y, bbi = bh >> 4, hh = bh & 15;
    const uint32_t smb = smem_u32(smc);
    const uint32_t sQh = smb;

    const size_t bhoff = (size_t)bh * SS * DD;
    const __half* Khg = g_khi + bhoff;
    const __half* Vhg = g_vhi + bhoff;

    const uint32_t b_ones[2] = {0x3C003C00u, 0x3C003C00u};

    const int aro  = (lane & 7) + 8 * ((lane >> 3) & 1);
    const int csel = 16 * (lane >> 4);

    auto load_kv = [&](int st, int kt) {
        uint32_t base = smb + AKV0 + st * ASTG;
        const int s0 = kt * 64;
#pragma unroll
        for (int i = 0; i < 2; i++) {
            int cid = tid + i * 256;
            int r = cid >> 3, c = cid & 7;
            uint32_t so = SWZ(r * 128 + c * 16);
            size_t go = (size_t)(s0 + r) * DD;
            CP16(base + so,        (const char*)(Khg + go) + c * 16);
            CP16(base + 8192 + so, (const char*)(Vhg + go) + c * 16);
        }
    };

    for (int qb = 0; qb < 2; qb++) {
        const int q0 = (blockIdx.x + qb * 8) * 128;
        const __half* Qhg = g_qhi + bhoff + (size_t)q0 * DD;

        __syncthreads();   // prior q-block fully consumed smem before rewrite

        // Q tile 128x64 fp16 = 16KB
#pragma unroll
        for (int i = 0; i < 4; i++) {
            int cid = tid + i * 256;
            int r = cid >> 3, c = cid & 7;
            uint32_t so = SWZ(r * 128 + c * 16);
            CP16(sQh + so, (const char*)(Qhg + (size_t)r * DD) + c * 16);
        }
        CP_COMMIT();
        load_kv(0, 0); CP_COMMIT();
        load_kv(1, 1); CP_COMMIT();
        if (tid < 64) {
            msk[0][tid] = mask[bbi * SS + tid] ? 0.f : -1e30f;
            msk[1][tid] = mask[bbi * SS + 64 + tid] ? 0.f : -1e30f;
        }
        CP_WAIT(2);
        __syncthreads();

        uint32_t qh[4][4];
#pragma unroll
        for (int ks = 0; ks < 4; ks++) {
            uint32_t off = SWZ((w * 16 + aro) * 128 + ks * 32 + csel);
            LDSM4(qh[ks][0], qh[ks][1], qh[ks][2], qh[ks][3], sQh + off);
        }

        float o[8][4];
#pragma unroll
        for (int j = 0; j < 8; j++)
#pragma unroll
            for (int q = 0; q < 4; q++) o[j][q] = 0.f;
        float mi0 = -1e30f, mi1 = -1e30f, li0 = 0.f, li1 = 0.f;

        for (int kt = 0; kt < 32; kt++) {
            const int st = kt % 3;
            if (kt < 31) { CP_WAIT(1); } else { CP_WAIT(0); }
            __syncthreads();
            if (kt + 2 < 32) {
                load_kv((kt + 2) % 3, kt + 2); CP_COMMIT();
                if (tid < 64)
                    msk[(kt + 2) % 3][tid] = mask[bbi * SS + (kt + 2) * 64 + tid] ? 0.f : -1e30f;
            }

            const uint32_t sKh = smb + AKV0 + st * ASTG;
            const uint32_t sVh = sKh + 8192;

            // S = q @ k^T
            float s[8][4];
#pragma unroll
            for (int j = 0; j < 8; j++)
#pragma unroll
                for (int q = 0; q < 4; q++) s[j][q] = 0.f;
#pragma unroll
            for (int ks = 0; ks < 4; ks++) {
                const int colb = ks * 32 + csel;
                uint32_t kb[8][2];
#pragma unroll
                for (int g = 0; g < 4; g++) {
                    uint32_t off = SWZ((g * 16 + aro) * 128 + colb);
                    uint32_t r0, r1, r2, r3;
                    LDSM4(r0, r1, r2, r3, sKh + off);
                    kb[2*g][0] = r0; kb[2*g][1] = r2; kb[2*g+1][0] = r1; kb[2*g+1][1] = r3;
                }
#pragma unroll
                for (int j = 0; j < 8; j++)
                    mma_f32(s[j], qh[ks], kb[j]);
            }

            // online softmax: mask + rowmax (f32), exp via ex2.f16x2
            const int c0 = (lane & 3) * 2;
            float mn0 = mi0, mn1 = mi1;
#pragma unroll
            for (int j = 0; j < 8; j++) {
                float mk0 = msk[st][j * 8 + c0], mk1 = msk[st][j * 8 + c0 + 1];
                s[j][0] += mk0; s[j][1] += mk1; s[j][2] += mk0; s[j][3] += mk1;
                mn0 = fmaxf(mn0, fmaxf(s[j][0], s[j][1]));
                mn1 = fmaxf(mn1, fmaxf(s[j][2], s[j][3]));
            }
            mn0 = fmaxf(mn0, __shfl_xor_sync(0xffffffffu, mn0, 1));
            mn0 = fmaxf(mn0, __shfl_xor_sync(0xffffffffu, mn0, 2));
            mn1 = fmaxf(mn1, __shfl_xor_sync(0xffffffffu, mn1, 1));
            mn1 = fmaxf(mn1, __shfl_xor_sync(0xffffffffu, mn1, 2));

            float a0 = __expf(mi0 - mn0), a1 = __expf(mi1 - mn1);
            float nl0 = mn0 * L2E, nl1 = mn1 * L2E;

            uint32_t pah[4][4];
#pragma unroll
            for (int j = 0; j < 8; j++) {
                float t0 = fmaf(s[j][0], L2E, -nl0);
                float t1 = fmaf(s[j][1], L2E, -nl0);
                float t2 = fmaf(s[j][2], L2E, -nl1);
                float t3 = fmaf(s[j][3], L2E, -nl1);
                pah[j >> 1][2*(j & 1) + 0] = exp2_f16x2(t0, t1);
                pah[j >> 1][2*(j & 1) + 1] = exp2_f16x2(t2, t3);
            }

            // row sums l += P @ 1 (exact f32 via tensor core, no shuffles)
            float rsum[4] = {0.f, 0.f, 0.f, 0.f};
#pragma unroll
            for (int ks = 0; ks < 4; ks++)
                mma_f32(rsum, pah[ks], b_ones);

            li0 = li0 * a0 + rsum[0];
            li1 = li1 * a1 + rsum[2];
            mi0 = mn0; mi1 = mn1;
#pragma unroll
            for (int j = 0; j < 8; j++) {
                o[j][0] *= a0; o[j][1] *= a0; o[j][2] *= a1; o[j][3] *= a1;
            }

            // O += p @ v
#pragma unroll
            for (int ks = 0; ks < 4; ks++) {
                uint32_t vb[8][2];
#pragma unroll
                for (int dt = 0; dt < 4; dt++) {
                    uint32_t off = SWZ((ks * 16 + (lane & 15)) * 128 + dt * 32 + csel);
                    uint32_t r0, r1, r2, r3;
                    LDSM4T(r0, r1, r2, r3, sVh + off);
                    vb[2*dt][0] = r0; vb[2*dt][1] = r1; vb[2*dt+1][0] = r2; vb[2*dt+1][1] = r3;
                }
#pragma unroll
                for (int j = 0; j < 8; j++)
                    mma_f32(o[j], pah[ks], vb[j]);
            }
        }

        // epilogue for this q-block
        float inv0 = 1.f / li0, inv1 = 1.f / li1;
        int r0 = q0 + w * 16 + (lane >> 2);
#pragma unroll
        for (int j = 0; j < 8; j++) {
            int d = j * 8 + (lane & 3) * 2;
            uint32_t h01 = packh(__float2half_rn(o[j][0] * inv0), __float2half_rn(o[j][1] * inv0));
            uint32_t h23 = packh(__float2half_rn(o[j][2] * inv1), __float2half_rn(o[j][3] * inv1));
            size_t i0 = (((size_t)bbi * SS + r0) * HH + hh) * DD + d;
            size_t i1 = (((size_t)bbi * SS + r0 + 8) * HH + hh) * DD + d;
            *(uint32_t*)&g_atthi[i0] = h01;
            *(uint32_t*)&g_atthi[i1] = h23;
        }
    }
}

// ---------------------------------------------------------------------------
extern "C" void kernel_launch(void* const* d_in, const int* in_sizes, int n_in,
                              void* d_out, int out_size)
{
    const float* x     = (const float*)d_in[0];
    const int*   mask  = (const int*)  d_in[1];
    const float* qkv_w = (const float*)d_in[2];
    const float* out_w = (const float*)d_in[3];
    const float* out_b = (const float*)d_in[4];
    float*       out   = (float*)d_out;

    __half *xhi, *wqhi, *wohi, *athi;
    cudaGetSymbolAddress((void**)&xhi,  g_xhi);
    cudaGetSymbolAddress((void**)&wqhi, g_wqhi);
    cudaGetSymbolAddress((void**)&wohi, g_wohi);
    cudaGetSymbolAddress((void**)&athi, g_atthi);

    cudaFuncSetAttribute(mm_mma,   cudaFuncAttributeMaxDynamicSharedMemorySize, GSMEM);
    cudaFuncSetAttribute(attn_mma, cudaFuncAttributeMaxDynamicSharedMemorySize, ASMEM);

    // 1) conversions
    {
        int n4 = M1 * KDIM / 4;
        conv_f16<<<(n4 + 255) / 256, 256>>>(x, xhi, n4);
        n4 = N1 * KDIM / 4;
        conv_f16<<<(n4 + 255) / 256, 256>>>(qkv_w, wqhi, n4);
        n4 = EE * KDIM / 4;
        conv_f16<<<(n4 + 255) / 256, 256>>>(out_w, wohi, n4);
    }

    // 2) QKV projection
    {
        dim3 grid(N1 / 128, M1 / 128);
        mm_mma<<<grid, 512, GSMEM>>>(xhi, wqhi, nullptr, nullptr, 0);
    }

    // 3) attention (single wave: 256 CTAs x 2 q-blocks)
    {
        dim3 grid(SS / 256, BB * HH);   // 8 x 32
        attn_mma<<<grid, 256, ASMEM>>>(mask);
    }

    // 4) output projection + bias
    {
        dim3 grid(EE / 128, M1 / 128);
        mm_mma<<<grid, 512, GSMEM>>>(athi, wohi, out, out_b, 1);
    }
}

// round 11
// speedup vs baseline: 2.5325x; 1.0004x over previous
#include <cuda_runtime.h>
#include <cuda_fp16.h>
#include <cstdint>

#define BB   2
#define SS   2048
#define EE   1024
#define HH   16
#define DD   64
#define M1   4096
#define N1   3072
#define KDIM 1024
#define SCALE 0.125f
#define L2E  1.4426950408889634f

// ---------------------------------------------------------------------------
// helpers
// ---------------------------------------------------------------------------
__device__ __forceinline__ uint32_t smem_u32(const void* p) {
    uint32_t a;
    asm("{ .reg .u64 t; cvta.to.shared.u64 t, %1; cvt.u32.u64 %0, t; }" : "=r"(a) : "l"(p));
    return a;
}
#define SWZ(x) ((x) ^ (((x) >> 3) & 0x70))

#define CP16(dst, src) \
    asm volatile("cp.async.cg.shared.global [%0], [%1], 16;" :: "r"(dst), "l"(src))
#define CP_COMMIT() asm volatile("cp.async.commit_group;" ::: "memory")
#define CP_WAIT(n)  asm volatile("cp.async.wait_group %0;" :: "n"(n) : "memory")

#define LDSM4(r0,r1,r2,r3,a) \
    asm volatile("ldmatrix.sync.aligned.m8n8.x4.shared.b16 {%0,%1,%2,%3}, [%4];" \
                 : "=r"(r0),"=r"(r1),"=r"(r2),"=r"(r3) : "r"(a))
#define LDSM4T(r0,r1,r2,r3,a) \
    asm volatile("ldmatrix.sync.aligned.m8n8.x4.trans.shared.b16 {%0,%1,%2,%3}, [%4];" \
                 : "=r"(r0),"=r"(r1),"=r"(r2),"=r"(r3) : "r"(a))

// fp16 inputs, fp32 accumulate
__device__ __forceinline__ void mma_f32(float* d, const uint32_t* a, const uint32_t* b) {
    asm volatile(
        "mma.sync.aligned.m16n8k16.row.col.f32.f16.f16.f32 "
        "{%0,%1,%2,%3}, {%4,%5,%6,%7}, {%8,%9}, {%0,%1,%2,%3};"
        : "+f"(d[0]), "+f"(d[1]), "+f"(d[2]), "+f"(d[3])
        : "r"(a[0]), "r"(a[1]), "r"(a[2]), "r"(a[3]), "r"(b[0]), "r"(b[1]));
}

__device__ __forceinline__ uint32_t packh(__half a, __half b) {
    __half2 t; t.x = a; t.y = b;
    return *reinterpret_cast<uint32_t*>(&t);
}
__device__ __forceinline__ float2 unpackh(uint32_t r) {
    __half2 h = *reinterpret_cast<__half2*>(&r);
    return __half22float2(h);
}

// pack (lo,hi) f32 pair -> half2, then 2^x on both lanes
__device__ __forceinline__ uint32_t exp2_f16x2(float lo, float hi) {
    uint32_t r;
    asm("cvt.rn.f16x2.f32 %0, %1, %2;" : "=r"(r) : "f"(hi), "f"(lo));
    asm("ex2.approx.f16x2 %0, %0;" : "+r"(r));
    return r;
}

// ---------------------------------------------------------------------------
// scratch (__device__ globals)
// ---------------------------------------------------------------------------
#define QKV_ELEMS ((size_t)BB*HH*SS*DD)
__device__ __half g_qhi[QKV_ELEMS];
__device__ __half g_khi[QKV_ELEMS];
__device__ __half g_vhi[QKV_ELEMS];
__device__ __half g_xhi[(size_t)M1*KDIM];
__device__ __half g_wqhi[(size_t)N1*KDIM];
__device__ __half g_wohi[(size_t)EE*KDIM];
__device__ __half g_atthi[(size_t)M1*EE];

// ---------------------------------------------------------------------------
// fused fp32 -> fp16 convert for all three tensors (one launch)
// ---------------------------------------------------------------------------
#define NX4  (M1*KDIM/4)          // 1048576
#define NWQ4 (N1*KDIM/4)          // 786432
#define NWO4 (EE*KDIM/4)          // 262144
#define NALL4 (NX4 + NWQ4 + NWO4) // 2097152

__global__ __launch_bounds__(256) void conv_all(const float* __restrict__ x,
                                                const float* __restrict__ wq,
                                                const float* __restrict__ wo,
                                                __half* __restrict__ xh,
                                                __half* __restrict__ wqh,
                                                __half* __restrict__ woh)
{
    int i = blockIdx.x * blockDim.x + threadIdx.x;
    const float* src; __half* dst; int off;
    if (i < NX4)              { src = x;  dst = xh;  off = i; }
    else if (i < NX4 + NWQ4)  { src = wq; dst = wqh; off = i - NX4; }
    else if (i < NALL4)       { src = wo; dst = woh; off = i - NX4 - NWQ4; }
    else return;
    float4 v = ((const float4*)src)[off];
    uint32_t h01 = packh(__float2half_rn(v.x), __float2half_rn(v.y));
    uint32_t h23 = packh(__float2half_rn(v.z), __float2half_rn(v.w));
    ((uint2*)dst)[off] = make_uint2(h01, h23);
}

// ---------------------------------------------------------------------------
// HMMA GEMM (pure fp16 in / fp32 acc): C = A @ B^T.  (unchanged)
// ---------------------------------------------------------------------------
#define GSTG 32768
#define GSMEM (3*GSTG)

__global__ __launch_bounds__(512, 1) void mm_mma(
    const __half* __restrict__ A, const __half* __restrict__ B,
    float* __restrict__ Cout, const float* __restrict__ bias, int mode)
{
    extern __shared__ char smc[];
    const int tid = threadIdx.x, lane = tid & 31, w = tid >> 5;
    const int wr = w >> 2, wc = w & 3;
    const int bm = blockIdx.y * 128, bn = blockIdx.x * 128;
    const uint32_t smb = smem_u32(smc);

    auto load_stage = [&](int st, int ch) {
        const int koff = ch * 64;
#pragma unroll
        for (int t = 0; t < 2; t++) {
            const __half* src = (t == 0) ? A : B;
            const int row0 = (t == 0) ? bm : bn;
#pragma unroll
            for (int i = 0; i < 2; i++) {
                int cid = tid + i * 512;
                int r = cid >> 3, c = cid & 7;
                uint32_t sa = smb + st * GSTG + t * 16384 + SWZ(r * 128 + c * 16);
                const char* ga = (const char*)(src + (size_t)(row0 + r) * KDIM + koff) + c * 16;
                CP16(sa, ga);
            }
        }
    };

    float acc[2][4][4];
#pragma unroll
    for (int i = 0; i < 2; i++)
#pragma unroll
        for (int j = 0; j < 4; j++)
#pragma unroll
            for (int q = 0; q < 4; q++) acc[i][j][q] = 0.f;

    load_stage(0, 0); CP_COMMIT();
    load_stage(1, 1); CP_COMMIT();

    const int aro  = (lane & 7) + 8 * ((lane >> 3) & 1);
    const int csel = 16 * (lane >> 4);

    for (int ch = 0; ch < 16; ch++) {
        const int st = ch % 3;
        if (ch < 15) { CP_WAIT(1); } else { CP_WAIT(0); }
        __syncthreads();
        if (ch + 2 < 16) { load_stage((ch + 2) % 3, ch + 2); CP_COMMIT(); }

        const uint32_t sA = smb + st * GSTG;
        const uint32_t sB = sA + 16384;

#pragma unroll
        for (int ks = 0; ks < 4; ks++) {
            const int colb = ks * 32 + csel;
            uint32_t ah[2][4];
#pragma unroll
            for (int i = 0; i < 2; i++) {
                uint32_t off = SWZ((wr * 32 + i * 16 + aro) * 128 + colb);
                LDSM4(ah[i][0], ah[i][1], ah[i][2], ah[i][3], sA + off);
            }
            uint32_t bhf[4][2];
#pragma unroll
            for (int g = 0; g < 2; g++) {
                uint32_t off = SWZ((wc * 32 + g * 16 + aro) * 128 + colb);
                uint32_t r0, r1, r2, r3;
                LDSM4(r0, r1, r2, r3, sB + off);
                bhf[2*g][0] = r0; bhf[2*g][1] = r2; bhf[2*g+1][0] = r1; bhf[2*g+1][1] = r3;
            }
#pragma unroll
            for (int i = 0; i < 2; i++)
#pragma unroll
                for (int j = 0; j < 4; j++)
                    mma_f32(acc[i][j], ah[i], bhf[j]);
        }
    }

#pragma unroll
    for (int i = 0; i < 2; i++) {
        int mrow = bm + wr * 32 + i * 16 + (lane >> 2);
#pragma unroll
        for (int j = 0; j < 4; j++) {
            int n = bn + wc * 32 + j * 8 + (lane & 3) * 2;
            if (mode == 0) {
                int c = n >> 10, h = (n >> 6) & 15, d = n & 63;
                float sc = (c == 0) ? SCALE : 1.0f;
                __half* dst = (c == 0) ? g_qhi : (c == 1) ? g_khi : g_vhi;
#pragma unroll
                for (int rr = 0; rr < 2; rr++) {
                    int m = mrow + rr * 8;
                    int b = m >> 11, s = m & 2047;
                    size_t idx = (((size_t)b * HH + h) * SS + s) * DD + d;
                    uint32_t hv = packh(__float2half_rn(acc[i][j][2*rr] * sc),
                                        __float2half_rn(acc[i][j][2*rr + 1] * sc));
                    *(uint32_t*)&dst[idx] = hv;
                }
            } else {
                float2 b2 = *(const float2*)&bias[n];
                *(float2*)&Cout[(size_t)mrow * EE + n] =
                    make_float2(acc[i][j][0] + b2.x, acc[i][j][1] + b2.y);
                *(float2*)&Cout[(size_t)(mrow + 8) * EE + n] =
                    make_float2(acc[i][j][2] + b2.x, acc[i][j][3] + b2.y);
            }
        }
    }
}

// ---------------------------------------------------------------------------
// FA2-style HMMA attention.
//  - grid (8, 32): 2 q-blocks per CTA (single wave at 2 CTAs/SM)
//  - softmax exp via ex2.approx.f16x2 (result IS the packed P fragment)
//  - row sums via f32 adds of the same packed f16 P values (ALU pipe is idle;
//    saves 4 tensor-pipe MMAs per tile)
// ---------------------------------------------------------------------------
#define AKV0 16384
#define ASTG 16384
#define ASMEM (AKV0 + 3*ASTG)   // 64 KB

__global__ __launch_bounds__(256, 2) void attn_mma(const int* __restrict__ mask)
{
    extern __shared__ char smc[];
    __shared__ float msk[3][64];
    const int tid = threadIdx.x, lane = tid & 31, w = tid >> 5;
    const int bh = blockIdx.y, bbi = bh >> 4, hh = bh & 15;
    const uint32_t smb = smem_u32(smc);
    const uint32_t sQh = smb;

    const size_t bhoff = (size_t)bh * SS * DD;
    const __half* Khg = g_khi + bhoff;
    const __half* Vhg = g_vhi + bhoff;

    const int aro  = (lane & 7) + 8 * ((lane >> 3) & 1);
    const int csel = 16 * (lane >> 4);

    auto load_kv = [&](int st, int kt) {
        uint32_t base = smb + AKV0 + st * ASTG;
        const int s0 = kt * 64;
#pragma unroll
        for (int i = 0; i < 2; i++) {
            int cid = tid + i * 256;
            int r = cid >> 3, c = cid & 7;
            uint32_t so = SWZ(r * 128 + c * 16);
            size_t go = (size_t)(s0 + r) * DD;
            CP16(base + so,        (const char*)(Khg + go) + c * 16);
            CP16(base + 8192 + so, (const char*)(Vhg + go) + c * 16);
        }
    };

    for (int qb = 0; qb < 2; qb++) {
        const int q0 = (blockIdx.x + qb * 8) * 128;
        const __half* Qhg = g_qhi + bhoff + (size_t)q0 * DD;

        __syncthreads();   // prior q-block fully consumed smem before rewrite

#pragma unroll
        for (int i = 0; i < 4; i++) {
            int cid = tid + i * 256;
            int r = cid >> 3, c = cid & 7;
            uint32_t so = SWZ(r * 128 + c * 16);
            CP16(sQh + so, (const char*)(Qhg + (size_t)r * DD) + c * 16);
        }
        CP_COMMIT();
        load_kv(0, 0); CP_COMMIT();
        load_kv(1, 1); CP_COMMIT();
        if (tid < 64) {
            msk[0][tid] = mask[bbi * SS + tid] ? 0.f : -1e30f;
            msk[1][tid] = mask[bbi * SS + 64 + tid] ? 0.f : -1e30f;
        }
        CP_WAIT(2);
        __syncthreads();

        uint32_t qh[4][4];
#pragma unroll
        for (int ks = 0; ks < 4; ks++) {
            uint32_t off = SWZ((w * 16 + aro) * 128 + ks * 32 + csel);
            LDSM4(qh[ks][0], qh[ks][1], qh[ks][2], qh[ks][3], sQh + off);
        }

        float o[8][4];
#pragma unroll
        for (int j = 0; j < 8; j++)
#pragma unroll
            for (int q = 0; q < 4; q++) o[j][q] = 0.f;
        float mi0 = -1e30f, mi1 = -1e30f, li0 = 0.f, li1 = 0.f;

        for (int kt = 0; kt < 32; kt++) {
            const int st = kt % 3;
            if (kt < 31) { CP_WAIT(1); } else { CP_WAIT(0); }
            __syncthreads();
            if (kt + 2 < 32) {
                load_kv((kt + 2) % 3, kt + 2); CP_COMMIT();
                if (tid < 64)
                    msk[(kt + 2) % 3][tid] = mask[bbi * SS + (kt + 2) * 64 + tid] ? 0.f : -1e30f;
            }

            const uint32_t sKh = smb + AKV0 + st * ASTG;
            const uint32_t sVh = sKh + 8192;

            // S = q @ k^T
            float s[8][4];
#pragma unroll
            for (int j = 0; j < 8; j++)
#pragma unroll
                for (int q = 0; q < 4; q++) s[j][q] = 0.f;
#pragma unroll
            for (int ks = 0; ks < 4; ks++) {
                const int colb = ks * 32 + csel;
                uint32_t kb[8][2];
#pragma unroll
                for (int g = 0; g < 4; g++) {
                    uint32_t off = SWZ((g * 16 + aro) * 128 + colb);
                    uint32_t r0, r1, r2, r3;
                    LDSM4(r0, r1, r2, r3, sKh + off);
                    kb[2*g][0] = r0; kb[2*g][1] = r2; kb[2*g+1][0] = r1; kb[2*g+1][1] = r3;
                }
#pragma unroll
                for (int j = 0; j < 8; j++)
                    mma_f32(s[j], qh[ks], kb[j]);
            }

            // online softmax: mask + rowmax (f32), exp via ex2.f16x2
            const int c0 = (lane & 3) * 2;
            float mn0 = mi0, mn1 = mi1;
#pragma unroll
            for (int j = 0; j < 8; j++) {
                float mk0 = msk[st][j * 8 + c0], mk1 = msk[st][j * 8 + c0 + 1];
                s[j][0] += mk0; s[j][1] += mk1; s[j][2] += mk0; s[j][3] += mk1;
                mn0 = fmaxf(mn0, fmaxf(s[j][0], s[j][1]));
                mn1 = fmaxf(mn1, fmaxf(s[j][2], s[j][3]));
            }
            mn0 = fmaxf(mn0, __shfl_xor_sync(0xffffffffu, mn0, 1));
            mn0 = fmaxf(mn0, __shfl_xor_sync(0xffffffffu, mn0, 2));
            mn1 = fmaxf(mn1, __shfl_xor_sync(0xffffffffu, mn1, 1));
            mn1 = fmaxf(mn1, __shfl_xor_sync(0xffffffffu, mn1, 2));

            float a0 = __expf(mi0 - mn0), a1 = __expf(mi1 - mn1);
            float nl0 = mn0 * L2E, nl1 = mn1 * L2E;

            uint32_t pah[4][4];
#pragma unroll
            for (int j = 0; j < 8; j++) {
                float t0 = fmaf(s[j][0], L2E, -nl0);
                float t1 = fmaf(s[j][1], L2E, -nl0);
                float t2 = fmaf(s[j][2], L2E, -nl1);
                float t3 = fmaf(s[j][3], L2E, -nl1);
                pah[j >> 1][2*(j & 1) + 0] = exp2_f16x2(t0, t1);
                pah[j >> 1][2*(j & 1) + 1] = exp2_f16x2(t2, t3);
            }

            // row sums: f32 adds of the packed f16 P values (ALU, not tensor)
            float rs0 = 0.f, rs1 = 0.f;
#pragma unroll
            for (int k = 0; k < 4; k++) {
                float2 a = unpackh(pah[k][0]); rs0 += a.x + a.y;
                float2 b = unpackh(pah[k][2]); rs0 += b.x + b.y;
                float2 c = unpackh(pah[k][1]); rs1 += c.x + c.y;
                float2 d = unpackh(pah[k][3]); rs1 += d.x + d.y;
            }
            rs0 += __shfl_xor_sync(0xffffffffu, rs0, 1);
            rs0 += __shfl_xor_sync(0xffffffffu, rs0, 2);
            rs1 += __shfl_xor_sync(0xffffffffu, rs1, 1);
            rs1 += __shfl_xor_sync(0xffffffffu, rs1, 2);

            li0 = li0 * a0 + rs0;
            li1 = li1 * a1 + rs1;
            mi0 = mn0; mi1 = mn1;
#pragma unroll
            for (int j = 0; j < 8; j++) {
                o[j][0] *= a0; o[j][1] *= a0; o[j][2] *= a1; o[j][3] *= a1;
            }

            // O += p @ v
#pragma unroll
            for (int ks = 0; ks < 4; ks++) {
                uint32_t vb[8][2];
#pragma unroll
                for (int dt = 0; dt < 4; dt++) {
                    uint32_t off = SWZ((ks * 16 + (lane & 15)) * 128 + dt * 32 + csel);
                    uint32_t r0, r1, r2, r3;
                    LDSM4T(r0, r1, r2, r3, sVh + off);
                    vb[2*dt][0] = r0; vb[2*dt][1] = r1; vb[2*dt+1][0] = r2; vb[2*dt+1][1] = r3;
                }
#pragma unroll
                for (int j = 0; j < 8; j++)
                    mma_f32(o[j], pah[ks], vb[j]);
            }
        }

        // epilogue for this q-block
        float inv0 = 1.f / li0, inv1 = 1.f / li1;
        int r0 = q0 + w * 16 + (lane >> 2);
#pragma unroll
        for (int j = 0; j < 8; j++) {
            int d = j * 8 + (lane & 3) * 2;
            uint32_t h01 = packh(__float2half_rn(o[j][0] * inv0), __float2half_rn(o[j][1] * inv0));
            uint32_t h23 = packh(__float2half_rn(o[j][2] * inv1), __float2half_rn(o[j][3] * inv1));
            size_t i0 = (((size_t)bbi * SS + r0) * HH + hh) * DD + d;
            size_t i1 = (((size_t)bbi * SS + r0 + 8) * HH + hh) * DD + d;
            *(uint32_t*)&g_atthi[i0] = h01;
            *(uint32_t*)&g_atthi[i1] = h23;
        }
    }
}

// ---------------------------------------------------------------------------
extern "C" void kernel_launch(void* const* d_in, const int* in_sizes, int n_in,
                              void* d_out, int out_size)
{
    const float* x     = (const float*)d_in[0];
    const int*   mask  = (const int*)  d_in[1];
    const float* qkv_w = (const float*)d_in[2];
    const float* out_w = (const float*)d_in[3];
    const float* out_b = (const float*)d_in[4];
    float*       out   = (float*)d_out;

    __half *xhi, *wqhi, *wohi, *athi;
    cudaGetSymbolAddress((void**)&xhi,  g_xhi);
    cudaGetSymbolAddress((void**)&wqhi, g_wqhi);
    cudaGetSymbolAddress((void**)&wohi, g_wohi);
    cudaGetSymbolAddress((void**)&athi, g_atthi);

    cudaFuncSetAttribute(mm_mma,   cudaFuncAttributeMaxDynamicSharedMemorySize, GSMEM);
    cudaFuncSetAttribute(attn_mma, cudaFuncAttributeMaxDynamicSharedMemorySize, ASMEM);

    // 1) fused conversions (one launch)
    conv_all<<<(NALL4 + 255) / 256, 256>>>(x, qkv_w, out_w, xhi, wqhi, wohi);

    // 2) QKV projection
    {
        dim3 grid(N1 / 128, M1 / 128);
        mm_mma<<<grid, 512, GSMEM>>>(xhi, wqhi, nullptr, nullptr, 0);
    }

    // 3) attention (single wave: 256 CTAs x 2 q-blocks)
    {
        dim3 grid(SS / 256, BB * HH);   // 8 x 32
        attn_mma<<<grid, 256, ASMEM>>>(mask);
    }

    // 4) output projection + bias
    {
        dim3 grid(EE / 128, M1 / 128);
        mm_mma<<<grid, 512, GSMEM>>>(athi, wohi, out, out_b, 1);
    }
}